// round 1
// baseline (speedup 1.0000x reference)
#include <cuda_runtime.h>
#include <math.h>

// Problem constants
#define B_SZ   8
#define T_LEN  1024
#define C_DIM  1024
#define H_NUM  16
#define D_HEAD 64
#define BH     (B_SZ * H_NUM)        // 128
#define M_ROWS (B_SZ * T_LEN)        // 8192
#define K_DIM  1024

// Scratch (device globals — no dynamic allocation allowed)
__device__ float g_q[BH * T_LEN * D_HEAD];
__device__ float g_k[BH * T_LEN * D_HEAD];
__device__ float g_v[BH * T_LEN * D_HEAD];
__device__ float g_y[M_ROWS * C_DIM];

// ---------------------------------------------------------------------------
// Tiled fp32 SGEMM: C[m][n] = sum_k A[m][k] * W[n][k]   (NT, K=1024)
// BM=BN=128, BK=16, 256 threads, 8x8 microtile.
// MODE 0: A = x, N=3072, epilogue scatters into g_q/g_k/g_v (B*H,T,D) layout.
// MODE 1: A = g_y, N=1024, epilogue writes Cout row-major.
// ---------------------------------------------------------------------------
template <int MODE>
__global__ __launch_bounds__(256) void sgemm_nt(const float* __restrict__ A,
                                                const float* __restrict__ W,
                                                float* __restrict__ Cout) {
    __shared__ float As[16][128];
    __shared__ float Bs[16][128];

    const int bm = blockIdx.y * 128;
    const int bn = blockIdx.x * 128;
    const int tid = threadIdx.x;

    const int tr = (tid >> 4) << 3;   // 0..120 step 8
    const int tc = (tid & 15) << 3;   // 0..120 step 8

    const int arow = tid >> 2;        // 0..63
    const int akq  = (tid & 3) << 2;  // 0,4,8,12

    const float* Ab = (MODE == 0) ? A : g_y;

    float acc[8][8];
#pragma unroll
    for (int i = 0; i < 8; i++)
#pragma unroll
        for (int j = 0; j < 8; j++) acc[i][j] = 0.f;

    for (int kt = 0; kt < K_DIM; kt += 16) {
        float4 a0 = *(const float4*)(Ab + (size_t)(bm + arow) * K_DIM + kt + akq);
        float4 a1 = *(const float4*)(Ab + (size_t)(bm + arow + 64) * K_DIM + kt + akq);
        float4 b0 = *(const float4*)(W + (size_t)(bn + arow) * K_DIM + kt + akq);
        float4 b1 = *(const float4*)(W + (size_t)(bn + arow + 64) * K_DIM + kt + akq);

        As[akq + 0][arow] = a0.x; As[akq + 1][arow] = a0.y;
        As[akq + 2][arow] = a0.z; As[akq + 3][arow] = a0.w;
        As[akq + 0][arow + 64] = a1.x; As[akq + 1][arow + 64] = a1.y;
        As[akq + 2][arow + 64] = a1.z; As[akq + 3][arow + 64] = a1.w;
        Bs[akq + 0][arow] = b0.x; Bs[akq + 1][arow] = b0.y;
        Bs[akq + 2][arow] = b0.z; Bs[akq + 3][arow] = b0.w;
        Bs[akq + 0][arow + 64] = b1.x; Bs[akq + 1][arow + 64] = b1.y;
        Bs[akq + 2][arow + 64] = b1.z; Bs[akq + 3][arow + 64] = b1.w;
        __syncthreads();

#pragma unroll
        for (int k = 0; k < 16; k++) {
            float av[8], bv[8];
            *(float4*)(av)     = *(const float4*)&As[k][tr];
            *(float4*)(av + 4) = *(const float4*)&As[k][tr + 4];
            *(float4*)(bv)     = *(const float4*)&Bs[k][tc];
            *(float4*)(bv + 4) = *(const float4*)&Bs[k][tc + 4];
#pragma unroll
            for (int i = 0; i < 8; i++)
#pragma unroll
                for (int j = 0; j < 8; j++) acc[i][j] += av[i] * bv[j];
        }
        __syncthreads();
    }

    if (MODE == 0) {
        // scatter qkv into head layout: n -> (part, h, d); m -> (b, t)
#pragma unroll
        for (int i = 0; i < 8; i++) {
            const int m = bm + tr + i;
            const int b = m >> 10;
            const int t = m & 1023;
#pragma unroll
            for (int j = 0; j < 8; j++) {
                const int n = bn + tc + j;
                const int part = n >> 10;
                const int c = n & 1023;
                const int h = c >> 6;
                const int d = c & 63;
                float* dst = (part == 0) ? g_q : (part == 1) ? g_k : g_v;
                dst[(((b << 4) + h) * T_LEN + t) * D_HEAD + d] = acc[i][j];
            }
        }
    } else {
#pragma unroll
        for (int i = 0; i < 8; i++) {
            const int m = bm + tr + i;
            float4 v0 = make_float4(acc[i][0], acc[i][1], acc[i][2], acc[i][3]);
            float4 v1 = make_float4(acc[i][4], acc[i][5], acc[i][6], acc[i][7]);
            *(float4*)&Cout[(size_t)m * 1024 + bn + tc]     = v0;
            *(float4*)&Cout[(size_t)m * 1024 + bn + tc + 4] = v1;
        }
    }
}

// ---------------------------------------------------------------------------
// Rotary: cos/sin computed from q itself, applied to both q and k (in place).
// One thread owns one (bh, t) row fully -> no cross-thread hazard.
// rot[j] = -x[2j+1] (j<32) ; rot[j] = x[2(j-32)] (j>=32)
// ---------------------------------------------------------------------------
__global__ __launch_bounds__(256) void rotary_kernel() {
    const int idx = blockIdx.x * blockDim.x + threadIdx.x;  // bh*T + t
    if (idx >= BH * T_LEN) return;
    float* qp = g_q + (size_t)idx * D_HEAD;
    float* kp = g_k + (size_t)idx * D_HEAD;

    float q[64], k[64];
#pragma unroll
    for (int i = 0; i < 16; i++) {
        ((float4*)q)[i] = ((const float4*)qp)[i];
        ((float4*)k)[i] = ((const float4*)kp)[i];
    }
#pragma unroll
    for (int dq = 0; dq < 16; dq++) {
        float4 qo, ko;
        float* qop = &qo.x;
        float* kop = &ko.x;
#pragma unroll
        for (int e = 0; e < 4; e++) {
            const int d = dq * 4 + e;
            float c, sn;
            sincosf(q[d], &sn, &c);
            const float rq = (d < 32) ? -q[2 * d + 1] : q[2 * (d - 32)];
            const float rk = (d < 32) ? -k[2 * d + 1] : k[2 * (d - 32)];
            qop[e] = q[d] * c + rq * sn;
            kop[e] = k[d] * c + rk * sn;
        }
        ((float4*)qp)[dq] = qo;
        ((float4*)kp)[dq] = ko;
    }
}

// ---------------------------------------------------------------------------
// Flash attention (causal, scale=1.0, fp32). Grid: (T/128, BH), 128 threads.
// Each thread owns one query row: q[64], o[64], s[64] register-resident.
// K/V tiles (64x64) staged in smem; all reads are warp-broadcast (no conflicts).
// ---------------------------------------------------------------------------
__global__ __launch_bounds__(128) void attn_kernel() {
    const int bh  = blockIdx.y;
    const int q0  = blockIdx.x * 128;
    const int tid = threadIdx.x;
    const int row = q0 + tid;

    __shared__ float4 ks[64 * 16];
    __shared__ float4 vs[64 * 16];

    const float* qptr = g_q + ((size_t)bh * T_LEN + row) * D_HEAD;
    float q[64];
#pragma unroll
    for (int i = 0; i < 16; i++) ((float4*)q)[i] = ((const float4*)qptr)[i];

    float o[64];
#pragma unroll
    for (int i = 0; i < 64; i++) o[i] = 0.f;
    float mI = -3.0e38f;
    float l = 0.f;

    for (int j0 = 0; j0 <= q0 + 64; j0 += 64) {
        const float4* kg = (const float4*)(g_k + ((size_t)bh * T_LEN + j0) * D_HEAD);
        const float4* vg = (const float4*)(g_v + ((size_t)bh * T_LEN + j0) * D_HEAD);
#pragma unroll
        for (int i = 0; i < 8; i++) {
            ks[tid + i * 128] = kg[tid + i * 128];
            vs[tid + i * 128] = vg[tid + i * 128];
        }
        __syncthreads();

        float s[64];
#pragma unroll
        for (int j = 0; j < 64; j++) {
            float sj = 0.f;
#pragma unroll
            for (int dq = 0; dq < 16; dq++) {
                const float4 kv = ks[j * 16 + dq];
                sj += q[dq * 4 + 0] * kv.x;
                sj += q[dq * 4 + 1] * kv.y;
                sj += q[dq * 4 + 2] * kv.z;
                sj += q[dq * 4 + 3] * kv.w;
            }
            s[j] = sj;
        }

        if (j0 + 63 > row) {  // diagonal tile: mask keys beyond the query index
#pragma unroll
            for (int j = 0; j < 64; j++)
                if (j0 + j > row) s[j] = -3.0e38f;
        }

        float mNew = mI;
#pragma unroll
        for (int j = 0; j < 64; j++) mNew = fmaxf(mNew, s[j]);

        const float corr = __expf(mI - mNew);
        l *= corr;
#pragma unroll
        for (int d = 0; d < 64; d++) o[d] *= corr;

#pragma unroll
        for (int j = 0; j < 64; j++) {
            const float p = __expf(s[j] - mNew);
            l += p;
#pragma unroll
            for (int dq = 0; dq < 16; dq++) {
                const float4 vv = vs[j * 16 + dq];
                o[dq * 4 + 0] += p * vv.x;
                o[dq * 4 + 1] += p * vv.y;
                o[dq * 4 + 2] += p * vv.z;
                o[dq * 4 + 3] += p * vv.w;
            }
        }
        mI = mNew;
        __syncthreads();
    }

    // write back to (B,T,C) layout for the projection GEMM
    const int b = bh >> 4;
    const int h = bh & 15;
    float* yp = g_y + ((size_t)(b * T_LEN + row)) * C_DIM + h * D_HEAD;
    const float inv = 1.f / l;
#pragma unroll
    for (int dq = 0; dq < 16; dq++) {
        float4 r = make_float4(o[dq * 4 + 0] * inv, o[dq * 4 + 1] * inv,
                               o[dq * 4 + 2] * inv, o[dq * 4 + 3] * inv);
        ((float4*)yp)[dq] = r;
    }
}

// ---------------------------------------------------------------------------
extern "C" void kernel_launch(void* const* d_in, const int* in_sizes, int n_in,
                              void* d_out, int out_size) {
    const float* x  = (const float*)d_in[0];   // (8,1024,1024)
    const float* Wa = (const float*)d_in[1];   // (3072,1024)
    const float* Wp = (const float*)d_in[2];   // (1024,1024)
    float* out = (float*)d_out;                // (8,1024,1024)

    // 1) QKV GEMM with head-layout scatter
    sgemm_nt<0><<<dim3(3072 / 128, M_ROWS / 128), 256>>>(x, Wa, nullptr);
    // 2) Rotary (cos/sin of q, applied to q and k)
    rotary_kernel<<<(BH * T_LEN) / 256, 256>>>();
    // 3) Causal flash attention
    attn_kernel<<<dim3(T_LEN / 128, BH), 128>>>();
    // 4) Output projection
    sgemm_nt<1><<<dim3(1024 / 128, M_ROWS / 128), 256>>>(nullptr, Wp, out);
}

// round 4
// speedup vs baseline: 1.6365x; 1.6365x over previous
#include <cuda_runtime.h>
#include <cuda_bf16.h>
#include <math.h>
#include <stdint.h>

// Problem constants
#define B_SZ   8
#define T_LEN  1024
#define C_DIM  1024
#define H_NUM  16
#define D_HEAD 64
#define BH     (B_SZ * H_NUM)        // 128
#define M_ROWS (B_SZ * T_LEN)        // 8192
#define K_DIM  1024

// fp32 scratch
__device__ float g_q[BH * T_LEN * D_HEAD];
__device__ float g_k[BH * T_LEN * D_HEAD];
__device__ float g_v[BH * T_LEN * D_HEAD];
__device__ float g_y[M_ROWS * C_DIM];

// bf16 split scratch (hi/lo decomposition for bf16x3 GEMM)
__device__ __nv_bfloat16 g_xhi[M_ROWS * K_DIM];
__device__ __nv_bfloat16 g_xlo[M_ROWS * K_DIM];
__device__ __nv_bfloat16 g_wahi[3 * C_DIM * K_DIM];
__device__ __nv_bfloat16 g_walo[3 * C_DIM * K_DIM];
__device__ __nv_bfloat16 g_wphi[C_DIM * K_DIM];
__device__ __nv_bfloat16 g_wplo[C_DIM * K_DIM];
__device__ __nv_bfloat16 g_yhi[M_ROWS * K_DIM];
__device__ __nv_bfloat16 g_ylo[M_ROWS * K_DIM];

// ---------------------------------------------------------------------------
// helpers
// ---------------------------------------------------------------------------
__device__ __forceinline__ uint32_t smem_u32(const void* p) {
    uint32_t a;
    asm("{ .reg .u64 t; cvta.to.shared.u64 t, %1; cvt.u32.u64 %0, t; }"
        : "=r"(a) : "l"(p));
    return a;
}

__device__ __forceinline__ void cp16(uint32_t dst, const void* src) {
    asm volatile("cp.async.cg.shared.global [%0], [%1], 16;" :: "r"(dst), "l"(src));
}
__device__ __forceinline__ void cp_commit() {
    asm volatile("cp.async.commit_group;" ::: "memory");
}
__device__ __forceinline__ void cp_wait1() {
    asm volatile("cp.async.wait_group 1;" ::: "memory");
}
__device__ __forceinline__ void cp_wait0() {
    asm volatile("cp.async.wait_group 0;" ::: "memory");
}

__device__ __forceinline__ void ldmat4(uint32_t* r, uint32_t addr) {
    asm volatile("ldmatrix.sync.aligned.m8n8.x4.shared.b16 {%0,%1,%2,%3}, [%4];"
                 : "=r"(r[0]), "=r"(r[1]), "=r"(r[2]), "=r"(r[3]) : "r"(addr));
}
__device__ __forceinline__ void ldmat2(uint32_t* r, uint32_t addr) {
    asm volatile("ldmatrix.sync.aligned.m8n8.x2.shared.b16 {%0,%1}, [%2];"
                 : "=r"(r[0]), "=r"(r[1]) : "r"(addr));
}

__device__ __forceinline__ void mma16816(float* c, const uint32_t* a, const uint32_t* b) {
    asm volatile(
        "mma.sync.aligned.m16n8k16.row.col.f32.bf16.bf16.f32 "
        "{%0,%1,%2,%3}, {%4,%5,%6,%7}, {%8,%9}, {%0,%1,%2,%3};"
        : "+f"(c[0]), "+f"(c[1]), "+f"(c[2]), "+f"(c[3])
        : "r"(a[0]), "r"(a[1]), "r"(a[2]), "r"(a[3]), "r"(b[0]), "r"(b[1]));
}

// ---------------------------------------------------------------------------
// fp32 -> (bf16 hi, bf16 lo) split
// ---------------------------------------------------------------------------
__global__ __launch_bounds__(256) void split_kernel(const float* __restrict__ src,
                                                    __nv_bfloat16* __restrict__ hi,
                                                    __nv_bfloat16* __restrict__ lo,
                                                    int n4) {
    int i = blockIdx.x * blockDim.x + threadIdx.x;
    if (i >= n4) return;
    float4 x = ((const float4*)src)[i];
    float xs[4] = {x.x, x.y, x.z, x.w};
    __nv_bfloat16 h[4], l[4];
#pragma unroll
    for (int e = 0; e < 4; e++) {
        h[e] = __float2bfloat16(xs[e]);
        l[e] = __float2bfloat16(xs[e] - __bfloat162float(h[e]));
    }
    ((uint2*)hi)[i] = *(uint2*)h;
    ((uint2*)lo)[i] = *(uint2*)l;
}

// ---------------------------------------------------------------------------
// mma.sync bf16x3 GEMM: D[m][n] = sum_k A[m][k]*B[n][k]  (K-major, K=1024)
// 128x128 tile, BK=64 double-buffered cp.async, 256 thr = 8 warps (64x32 each)
// MODE 0: scatter into g_q/g_k/g_v head layout. MODE 1: row-major Cout.
// ---------------------------------------------------------------------------
#define SKE 72                       // smem row stride (elems): pad for ldmatrix
#define SKB (SKE * 2)                // 144 bytes
#define TILE_B (128 * SKB)           // 18432 bytes per 128x64 tile
#define DSMEM (2 * 4 * TILE_B)       // 147456 bytes (2 bufs x {Ahi,Alo,Bhi,Blo})

template <int MODE>
__global__ __launch_bounds__(256, 1) void gemm_mma(
    const __nv_bfloat16* __restrict__ Ahi, const __nv_bfloat16* __restrict__ Alo,
    const __nv_bfloat16* __restrict__ Bhi, const __nv_bfloat16* __restrict__ Blo,
    float* __restrict__ Cout) {
    extern __shared__ char dsm[];
    const uint32_t sbase = smem_u32(dsm);

    const int tid  = threadIdx.x;
    const int lane = tid & 31;
    const int wid  = tid >> 5;
    const int wm   = (wid & 1) * 64;   // warp m offset in tile
    const int wn   = (wid >> 1) * 32;  // warp n offset in tile
    const int bn   = blockIdx.x * 128;
    const int bm   = blockIdx.y * 128;

    float c[4][4][4];
#pragma unroll
    for (int mi = 0; mi < 4; mi++)
#pragma unroll
        for (int ni = 0; ni < 4; ni++)
#pragma unroll
            for (int e = 0; e < 4; e++) c[mi][ni][e] = 0.f;

    const __nv_bfloat16* srcs[4] = {Ahi, Alo, Bhi, Blo};
    const int gbase[2] = {bm, bn};

    // issue cp.async for one K-chunk (4 tiles of 128 rows x 64 bf16) into `buf`
    auto issue = [&](int ch, int buf) {
        const int k0 = ch * 64;
#pragma unroll
        for (int t = 0; t < 4; t++) {
            const __nv_bfloat16* src = srcs[t];
            const int gb = gbase[t >> 1];
            const uint32_t dbase = sbase + (uint32_t)(buf * 4 + t) * TILE_B;
#pragma unroll
            for (int it = 0; it < 4; it++) {
                const int idx = tid + it * 256;     // 0..1023
                const int row = idx >> 3;           // 0..127
                const int seg = idx & 7;            // 16B segment (8 per 128B row)
                cp16(dbase + (uint32_t)row * SKB + seg * 16,
                     src + (size_t)(gb + row) * K_DIM + k0 + seg * 8);
            }
        }
        cp_commit();
    };

    issue(0, 0);

    for (int ch = 0; ch < 16; ch++) {
        if (ch < 15) { issue(ch + 1, (ch + 1) & 1); cp_wait1(); }
        else         { cp_wait0(); }
        __syncthreads();

        const uint32_t abase = sbase + (uint32_t)((ch & 1) * 4 + 0) * TILE_B;
        const uint32_t bbase = sbase + (uint32_t)((ch & 1) * 4 + 2) * TILE_B;

        const int arow = lane & 15;
        const int acol = (lane >> 4) << 3;
        const int brow = lane & 7;
        const int bcol = ((lane >> 3) & 1) << 3;

#pragma unroll
        for (int k16 = 0; k16 < 4; k16++) {
            uint32_t ah[4][4], al[4][4], bh[4][2], bl[4][2];
#pragma unroll
            for (int mi = 0; mi < 4; mi++) {
                const uint32_t ad = abase + (uint32_t)(wm + mi * 16 + arow) * SKB
                                  + (uint32_t)(k16 * 16 + acol) * 2;
                ldmat4(ah[mi], ad);
                ldmat4(al[mi], ad + TILE_B);
            }
#pragma unroll
            for (int ni = 0; ni < 4; ni++) {
                const uint32_t bd = bbase + (uint32_t)(wn + ni * 8 + brow) * SKB
                                  + (uint32_t)(k16 * 16 + bcol) * 2;
                ldmat2(bh[ni], bd);
                ldmat2(bl[ni], bd + TILE_B);
            }
#pragma unroll
            for (int mi = 0; mi < 4; mi++)
#pragma unroll
                for (int ni = 0; ni < 4; ni++) {
                    mma16816(c[mi][ni], ah[mi], bh[ni]);
                    mma16816(c[mi][ni], ah[mi], bl[ni]);
                    mma16816(c[mi][ni], al[mi], bh[ni]);
                }
        }
        __syncthreads();
    }

    // epilogue: c0:(g,2tg) c1:(g,2tg+1) c2:(g+8,2tg) c3:(g+8,2tg+1)
    const int g  = lane >> 2;
    const int tg = lane & 3;
#pragma unroll
    for (int mi = 0; mi < 4; mi++) {
#pragma unroll
        for (int ni = 0; ni < 4; ni++) {
            const int n = bn + wn + ni * 8 + 2 * tg;
            const int m0r = bm + wm + mi * 16 + g;
            float2 v0 = make_float2(c[mi][ni][0], c[mi][ni][1]);
            float2 v1 = make_float2(c[mi][ni][2], c[mi][ni][3]);
            if (MODE == 0) {
                const int part = n >> 10;
                const int cc = n & 1023;
                const int h = cc >> 6;
                const int d = cc & 63;
                float* dst = (part == 0) ? g_q : (part == 1) ? g_k : g_v;
#pragma unroll
                for (int rr = 0; rr < 2; rr++) {
                    const int m = m0r + rr * 8;
                    const int b = m >> 10;
                    const int t = m & 1023;
                    *(float2*)(dst + (((size_t)(b * 16 + h) * T_LEN + t) * D_HEAD + d)) =
                        rr ? v1 : v0;
                }
            } else {
                *(float2*)(Cout + (size_t)m0r * C_DIM + n) = v0;
                *(float2*)(Cout + (size_t)(m0r + 8) * C_DIM + n) = v1;
            }
        }
    }
}

// ---------------------------------------------------------------------------
// Rotary: cos/sin of q applied to both q and k (in place). One thread per row.
// ---------------------------------------------------------------------------
__global__ __launch_bounds__(256) void rotary_kernel() {
    const int idx = blockIdx.x * blockDim.x + threadIdx.x;
    if (idx >= BH * T_LEN) return;
    float* qp = g_q + (size_t)idx * D_HEAD;
    float* kp = g_k + (size_t)idx * D_HEAD;

    float q[64], k[64];
#pragma unroll
    for (int i = 0; i < 16; i++) {
        ((float4*)q)[i] = ((const float4*)qp)[i];
        ((float4*)k)[i] = ((const float4*)kp)[i];
    }
#pragma unroll
    for (int dq = 0; dq < 16; dq++) {
        float4 qo, ko;
        float* qop = &qo.x;
        float* kop = &ko.x;
#pragma unroll
        for (int e = 0; e < 4; e++) {
            const int d = dq * 4 + e;
            float cc, sn;
            sincosf(q[d], &sn, &cc);
            const float rq = (d < 32) ? -q[2 * d + 1] : q[2 * (d - 32)];
            const float rk = (d < 32) ? -k[2 * d + 1] : k[2 * (d - 32)];
            qop[e] = q[d] * cc + rq * sn;
            kop[e] = k[d] * cc + rk * sn;
        }
        ((float4*)qp)[dq] = qo;
        ((float4*)kp)[dq] = ko;
    }
}

// ---------------------------------------------------------------------------
// Flash attention (causal, scale=1.0, fp32). Grid: (T/128, BH), 128 threads.
// ---------------------------------------------------------------------------
__global__ __launch_bounds__(128) void attn_kernel() {
    const int bh  = blockIdx.y;
    const int q0  = blockIdx.x * 128;
    const int tid = threadIdx.x;
    const int row = q0 + tid;

    __shared__ float4 ks[64 * 16];
    __shared__ float4 vs[64 * 16];

    const float* qptr = g_q + ((size_t)bh * T_LEN + row) * D_HEAD;
    float q[64];
#pragma unroll
    for (int i = 0; i < 16; i++) ((float4*)q)[i] = ((const float4*)qptr)[i];

    float o[64];
#pragma unroll
    for (int i = 0; i < 64; i++) o[i] = 0.f;
    float mI = -3.0e38f;
    float l = 0.f;

    for (int j0 = 0; j0 <= q0 + 64; j0 += 64) {
        const float4* kg = (const float4*)(g_k + ((size_t)bh * T_LEN + j0) * D_HEAD);
        const float4* vg = (const float4*)(g_v + ((size_t)bh * T_LEN + j0) * D_HEAD);
#pragma unroll
        for (int i = 0; i < 8; i++) {
            ks[tid + i * 128] = kg[tid + i * 128];
            vs[tid + i * 128] = vg[tid + i * 128];
        }
        __syncthreads();

        float s[64];
#pragma unroll
        for (int j = 0; j < 64; j++) {
            float sj = 0.f;
#pragma unroll
            for (int dq = 0; dq < 16; dq++) {
                const float4 kv = ks[j * 16 + dq];
                sj += q[dq * 4 + 0] * kv.x;
                sj += q[dq * 4 + 1] * kv.y;
                sj += q[dq * 4 + 2] * kv.z;
                sj += q[dq * 4 + 3] * kv.w;
            }
            s[j] = sj;
        }

        if (j0 + 63 > row) {
#pragma unroll
            for (int j = 0; j < 64; j++)
                if (j0 + j > row) s[j] = -3.0e38f;
        }

        float mNew = mI;
#pragma unroll
        for (int j = 0; j < 64; j++) mNew = fmaxf(mNew, s[j]);

        const float corr = __expf(mI - mNew);
        l *= corr;
#pragma unroll
        for (int d = 0; d < 64; d++) o[d] *= corr;

#pragma unroll
        for (int j = 0; j < 64; j++) {
            const float p = __expf(s[j] - mNew);
            l += p;
#pragma unroll
            for (int dq = 0; dq < 16; dq++) {
                const float4 vv = vs[j * 16 + dq];
                o[dq * 4 + 0] += p * vv.x;
                o[dq * 4 + 1] += p * vv.y;
                o[dq * 4 + 2] += p * vv.z;
                o[dq * 4 + 3] += p * vv.w;
            }
        }
        mI = mNew;
        __syncthreads();
    }

    const int b = bh >> 4;
    const int h = bh & 15;
    float* yp = g_y + ((size_t)(b * T_LEN + row)) * C_DIM + h * D_HEAD;
    const float inv = 1.f / l;
#pragma unroll
    for (int dq = 0; dq < 16; dq++) {
        float4 r = make_float4(o[dq * 4 + 0] * inv, o[dq * 4 + 1] * inv,
                               o[dq * 4 + 2] * inv, o[dq * 4 + 3] * inv);
        ((float4*)yp)[dq] = r;
    }
}

// ---------------------------------------------------------------------------
extern "C" void kernel_launch(void* const* d_in, const int* in_sizes, int n_in,
                              void* d_out, int out_size) {
    const float* x  = (const float*)d_in[0];   // (8,1024,1024)
    const float* Wa = (const float*)d_in[1];   // (3072,1024)
    const float* Wp = (const float*)d_in[2];   // (1024,1024)
    float* out = (float*)d_out;                // (8,1024,1024)

    cudaFuncSetAttribute(gemm_mma<0>, cudaFuncAttributeMaxDynamicSharedMemorySize, DSMEM);
    cudaFuncSetAttribute(gemm_mma<1>, cudaFuncAttributeMaxDynamicSharedMemorySize, DSMEM);

    __nv_bfloat16 *xhi, *xlo, *wahi, *walo, *wphi, *wplo, *yhi, *ylo;
    float *yd;
    cudaGetSymbolAddress((void**)&xhi,  g_xhi);
    cudaGetSymbolAddress((void**)&xlo,  g_xlo);
    cudaGetSymbolAddress((void**)&wahi, g_wahi);
    cudaGetSymbolAddress((void**)&walo, g_walo);
    cudaGetSymbolAddress((void**)&wphi, g_wphi);
    cudaGetSymbolAddress((void**)&wplo, g_wplo);
    cudaGetSymbolAddress((void**)&yhi,  g_yhi);
    cudaGetSymbolAddress((void**)&ylo,  g_ylo);
    cudaGetSymbolAddress((void**)&yd,   g_y);

    // 1) fp32 -> bf16 hi/lo splits
    split_kernel<<<(M_ROWS * K_DIM / 4) / 256, 256>>>(x,  xhi,  xlo,  M_ROWS * K_DIM / 4);
    split_kernel<<<(3 * C_DIM * K_DIM / 4) / 256, 256>>>(Wa, wahi, walo, 3 * C_DIM * K_DIM / 4);
    split_kernel<<<(C_DIM * K_DIM / 4) / 256, 256>>>(Wp, wphi, wplo, C_DIM * K_DIM / 4);

    // 2) QKV GEMM (mma.sync bf16x3) with head-layout scatter
    gemm_mma<0><<<dim3(3072 / 128, M_ROWS / 128), 256, DSMEM>>>(xhi, xlo, wahi, walo, nullptr);

    // 3) Rotary
    rotary_kernel<<<(BH * T_LEN) / 256, 256>>>();

    // 4) Causal flash attention (fp32)
    attn_kernel<<<dim3(T_LEN / 128, BH), 128>>>();

    // 5) Split attention output, then projection GEMM
    split_kernel<<<(M_ROWS * K_DIM / 4) / 256, 256>>>(yd, yhi, ylo, M_ROWS * K_DIM / 4);
    gemm_mma<1><<<dim3(1024 / 128, M_ROWS / 128), 256, DSMEM>>>(yhi, ylo, wphi, wplo, out);
}

// round 5
// speedup vs baseline: 3.5227x; 2.1526x over previous
#include <cuda_runtime.h>
#include <cuda_bf16.h>
#include <math.h>
#include <stdint.h>

// Problem constants
#define B_SZ   8
#define T_LEN  1024
#define C_DIM  1024
#define H_NUM  16
#define D_HEAD 64
#define BH     (B_SZ * H_NUM)        // 128
#define M_ROWS (B_SZ * T_LEN)        // 8192
#define K_DIM  1024

// fp32 scratch (pre-rotary q/k only)
__device__ float g_q[BH * T_LEN * D_HEAD];
__device__ float g_k[BH * T_LEN * D_HEAD];

// bf16 hi/lo split buffers
__device__ __nv_bfloat16 g_xhi[M_ROWS * K_DIM];
__device__ __nv_bfloat16 g_xlo[M_ROWS * K_DIM];
__device__ __nv_bfloat16 g_wahi[3 * C_DIM * K_DIM];
__device__ __nv_bfloat16 g_walo[3 * C_DIM * K_DIM];
__device__ __nv_bfloat16 g_wphi[C_DIM * K_DIM];
__device__ __nv_bfloat16 g_wplo[C_DIM * K_DIM];
__device__ __nv_bfloat16 g_qhi[BH * T_LEN * D_HEAD];
__device__ __nv_bfloat16 g_qlo[BH * T_LEN * D_HEAD];
__device__ __nv_bfloat16 g_khi[BH * T_LEN * D_HEAD];
__device__ __nv_bfloat16 g_klo[BH * T_LEN * D_HEAD];
__device__ __nv_bfloat16 g_vhi[BH * T_LEN * D_HEAD];
__device__ __nv_bfloat16 g_vlo[BH * T_LEN * D_HEAD];
__device__ __nv_bfloat16 g_yhi[M_ROWS * C_DIM];
__device__ __nv_bfloat16 g_ylo[M_ROWS * C_DIM];

// ---------------------------------------------------------------------------
// helpers
// ---------------------------------------------------------------------------
__device__ __forceinline__ uint32_t smem_u32(const void* p) {
    uint32_t a;
    asm("{ .reg .u64 t; cvta.to.shared.u64 t, %1; cvt.u32.u64 %0, t; }"
        : "=r"(a) : "l"(p));
    return a;
}
__device__ __forceinline__ void cp16(uint32_t dst, const void* src) {
    asm volatile("cp.async.cg.shared.global [%0], [%1], 16;" :: "r"(dst), "l"(src));
}
__device__ __forceinline__ void cp_commit() {
    asm volatile("cp.async.commit_group;" ::: "memory");
}
__device__ __forceinline__ void cp_wait1() {
    asm volatile("cp.async.wait_group 1;" ::: "memory");
}
__device__ __forceinline__ void cp_wait0() {
    asm volatile("cp.async.wait_group 0;" ::: "memory");
}
__device__ __forceinline__ void ldmat4(uint32_t* r, uint32_t addr) {
    asm volatile("ldmatrix.sync.aligned.m8n8.x4.shared.b16 {%0,%1,%2,%3}, [%4];"
                 : "=r"(r[0]), "=r"(r[1]), "=r"(r[2]), "=r"(r[3]) : "r"(addr));
}
__device__ __forceinline__ void ldmat2(uint32_t* r, uint32_t addr) {
    asm volatile("ldmatrix.sync.aligned.m8n8.x2.shared.b16 {%0,%1}, [%2];"
                 : "=r"(r[0]), "=r"(r[1]) : "r"(addr));
}
__device__ __forceinline__ void ldmat2t(uint32_t* r, uint32_t addr) {
    asm volatile("ldmatrix.sync.aligned.m8n8.x2.trans.shared.b16 {%0,%1}, [%2];"
                 : "=r"(r[0]), "=r"(r[1]) : "r"(addr));
}
__device__ __forceinline__ void mma16816(float* c, const uint32_t* a, const uint32_t* b) {
    asm volatile(
        "mma.sync.aligned.m16n8k16.row.col.f32.bf16.bf16.f32 "
        "{%0,%1,%2,%3}, {%4,%5,%6,%7}, {%8,%9}, {%0,%1,%2,%3};"
        : "+f"(c[0]), "+f"(c[1]), "+f"(c[2]), "+f"(c[3])
        : "r"(a[0]), "r"(a[1]), "r"(a[2]), "r"(a[3]), "r"(b[0]), "r"(b[1]));
}
// pack two fp32 -> bf16x2 (low = a, high = b)
__device__ __forceinline__ uint32_t packbf(float a, float b) {
    uint32_t r;
    asm("cvt.rn.bf16x2.f32 %0, %1, %2;" : "=r"(r) : "f"(b), "f"(a));
    return r;
}
__device__ __forceinline__ float qmax(float x) {
    x = fmaxf(x, __shfl_xor_sync(0xffffffffu, x, 1));
    x = fmaxf(x, __shfl_xor_sync(0xffffffffu, x, 2));
    return x;
}
__device__ __forceinline__ float qsum(float x) {
    x += __shfl_xor_sync(0xffffffffu, x, 1);
    x += __shfl_xor_sync(0xffffffffu, x, 2);
    return x;
}

// ---------------------------------------------------------------------------
// fp32 -> (bf16 hi, bf16 lo) split
// ---------------------------------------------------------------------------
__global__ __launch_bounds__(256) void split_kernel(const float* __restrict__ src,
                                                    __nv_bfloat16* __restrict__ hi,
                                                    __nv_bfloat16* __restrict__ lo,
                                                    int n4) {
    int i = blockIdx.x * blockDim.x + threadIdx.x;
    if (i >= n4) return;
    float4 x = ((const float4*)src)[i];
    float xs[4] = {x.x, x.y, x.z, x.w};
    __nv_bfloat16 h[4], l[4];
#pragma unroll
    for (int e = 0; e < 4; e++) {
        h[e] = __float2bfloat16(xs[e]);
        l[e] = __float2bfloat16(xs[e] - __bfloat162float(h[e]));
    }
    ((uint2*)hi)[i] = *(uint2*)h;
    ((uint2*)lo)[i] = *(uint2*)l;
}

// ---------------------------------------------------------------------------
// mma.sync bf16x3 GEMM (as round 4, epilogue updated)
// ---------------------------------------------------------------------------
#define SKE 72
#define SKB (SKE * 2)                // 144 bytes
#define TILE_B (128 * SKB)           // 18432
#define DSMEM (2 * 4 * TILE_B)       // 147456

template <int MODE>
__global__ __launch_bounds__(256, 1) void gemm_mma(
    const __nv_bfloat16* __restrict__ Ahi, const __nv_bfloat16* __restrict__ Alo,
    const __nv_bfloat16* __restrict__ Bhi, const __nv_bfloat16* __restrict__ Blo,
    float* __restrict__ Cout) {
    extern __shared__ char dsm[];
    const uint32_t sbase = smem_u32(dsm);

    const int tid  = threadIdx.x;
    const int lane = tid & 31;
    const int wid  = tid >> 5;
    const int wm   = (wid & 1) * 64;
    const int wn   = (wid >> 1) * 32;
    const int bn   = blockIdx.x * 128;
    const int bm   = blockIdx.y * 128;

    float c[4][4][4];
#pragma unroll
    for (int mi = 0; mi < 4; mi++)
#pragma unroll
        for (int ni = 0; ni < 4; ni++)
#pragma unroll
            for (int e = 0; e < 4; e++) c[mi][ni][e] = 0.f;

    const __nv_bfloat16* srcs[4] = {Ahi, Alo, Bhi, Blo};
    const int gbase[2] = {bm, bn};

    auto issue = [&](int ch, int buf) {
        const int k0 = ch * 64;
#pragma unroll
        for (int t = 0; t < 4; t++) {
            const __nv_bfloat16* src = srcs[t];
            const int gb = gbase[t >> 1];
            const uint32_t dbase = sbase + (uint32_t)(buf * 4 + t) * TILE_B;
#pragma unroll
            for (int it = 0; it < 4; it++) {
                const int idx = tid + it * 256;
                const int row = idx >> 3;
                const int seg = idx & 7;
                cp16(dbase + (uint32_t)row * SKB + seg * 16,
                     src + (size_t)(gb + row) * K_DIM + k0 + seg * 8);
            }
        }
        cp_commit();
    };

    issue(0, 0);

    for (int ch = 0; ch < 16; ch++) {
        if (ch < 15) { issue(ch + 1, (ch + 1) & 1); cp_wait1(); }
        else         { cp_wait0(); }
        __syncthreads();

        const uint32_t abase = sbase + (uint32_t)((ch & 1) * 4 + 0) * TILE_B;
        const uint32_t bbase = sbase + (uint32_t)((ch & 1) * 4 + 2) * TILE_B;

        const int arow = lane & 15;
        const int acol = (lane >> 4) << 3;
        const int brow = lane & 7;
        const int bcol = ((lane >> 3) & 1) << 3;

#pragma unroll
        for (int k16 = 0; k16 < 4; k16++) {
            uint32_t ah[4][4], al[4][4], bh[4][2], bl[4][2];
#pragma unroll
            for (int mi = 0; mi < 4; mi++) {
                const uint32_t ad = abase + (uint32_t)(wm + mi * 16 + arow) * SKB
                                  + (uint32_t)(k16 * 16 + acol) * 2;
                ldmat4(ah[mi], ad);
                ldmat4(al[mi], ad + TILE_B);
            }
#pragma unroll
            for (int ni = 0; ni < 4; ni++) {
                const uint32_t bd = bbase + (uint32_t)(wn + ni * 8 + brow) * SKB
                                  + (uint32_t)(k16 * 16 + bcol) * 2;
                ldmat2(bh[ni], bd);
                ldmat2(bl[ni], bd + TILE_B);
            }
#pragma unroll
            for (int mi = 0; mi < 4; mi++)
#pragma unroll
                for (int ni = 0; ni < 4; ni++) {
                    mma16816(c[mi][ni], ah[mi], bh[ni]);
                    mma16816(c[mi][ni], ah[mi], bl[ni]);
                    mma16816(c[mi][ni], al[mi], bh[ni]);
                }
        }
        __syncthreads();
    }

    const int g  = lane >> 2;
    const int tg = lane & 3;
#pragma unroll
    for (int mi = 0; mi < 4; mi++) {
#pragma unroll
        for (int ni = 0; ni < 4; ni++) {
            const int n = bn + wn + ni * 8 + 2 * tg;
            const int m0r = bm + wm + mi * 16 + g;
            if (MODE == 0) {
                const int part = n >> 10;
                const int cc = n & 1023;
                const int h = cc >> 6;
                const int d = cc & 63;
#pragma unroll
                for (int rr = 0; rr < 2; rr++) {
                    const int m = m0r + rr * 8;
                    const int b = m >> 10;
                    const int t = m & 1023;
                    const size_t off = ((size_t)(b * 16 + h) * T_LEN + t) * D_HEAD + d;
                    float2 v = rr ? make_float2(c[mi][ni][2], c[mi][ni][3])
                                  : make_float2(c[mi][ni][0], c[mi][ni][1]);
                    if (part == 0)      *(float2*)(g_q + off) = v;
                    else if (part == 1) *(float2*)(g_k + off) = v;
                    else {
                        // v: store bf16 hi/lo directly
                        uint32_t hi = packbf(v.x, v.y);
                        float hx = __bfloat162float(__float2bfloat16(v.x));
                        float hy = __bfloat162float(__float2bfloat16(v.y));
                        uint32_t lo = packbf(v.x - hx, v.y - hy);
                        *(uint32_t*)(g_vhi + off) = hi;
                        *(uint32_t*)(g_vlo + off) = lo;
                    }
                }
            } else {
                *(float2*)(Cout + (size_t)m0r * C_DIM + n) =
                    make_float2(c[mi][ni][0], c[mi][ni][1]);
                *(float2*)(Cout + (size_t)(m0r + 8) * C_DIM + n) =
                    make_float2(c[mi][ni][2], c[mi][ni][3]);
            }
        }
    }
}

// ---------------------------------------------------------------------------
// Rotary: reads fp32 g_q/g_k, writes bf16 hi/lo splits of rotated q,k.
// ---------------------------------------------------------------------------
__global__ __launch_bounds__(256) void rotary_kernel() {
    const int idx = blockIdx.x * blockDim.x + threadIdx.x;
    if (idx >= BH * T_LEN) return;
    const float* qp = g_q + (size_t)idx * D_HEAD;
    const float* kp = g_k + (size_t)idx * D_HEAD;

    float q[64], k[64];
#pragma unroll
    for (int i = 0; i < 16; i++) {
        ((float4*)q)[i] = ((const float4*)qp)[i];
        ((float4*)k)[i] = ((const float4*)kp)[i];
    }
    uint32_t* qh32 = (uint32_t*)g_qhi + (size_t)idx * 32;
    uint32_t* ql32 = (uint32_t*)g_qlo + (size_t)idx * 32;
    uint32_t* kh32 = (uint32_t*)g_khi + (size_t)idx * 32;
    uint32_t* kl32 = (uint32_t*)g_klo + (size_t)idx * 32;

#pragma unroll
    for (int i = 0; i < 32; i++) {
        float qo[2], ko[2];
#pragma unroll
        for (int e = 0; e < 2; e++) {
            const int d = 2 * i + e;
            float cc, sn;
            sincosf(q[d], &sn, &cc);
            const float rq = (d < 32) ? -q[2 * d + 1] : q[2 * d - 64];
            const float rk = (d < 32) ? -k[2 * d + 1] : k[2 * d - 64];
            qo[e] = q[d] * cc + rq * sn;
            ko[e] = k[d] * cc + rk * sn;
        }
        qh32[i] = packbf(qo[0], qo[1]);
        ql32[i] = packbf(qo[0] - __bfloat162float(__float2bfloat16(qo[0])),
                         qo[1] - __bfloat162float(__float2bfloat16(qo[1])));
        kh32[i] = packbf(ko[0], ko[1]);
        kl32[i] = packbf(ko[0] - __bfloat162float(__float2bfloat16(ko[0])),
                         ko[1] - __bfloat162float(__float2bfloat16(ko[1])));
    }
}

// ---------------------------------------------------------------------------
// Tensor-core flash attention (causal, scale=1.0).
// CTA: 128 q rows, 8 warps x 16 rows. KV tiles of 64, double-buffered cp.async.
// QK^T and PV both bf16x3 split for fp32-grade accuracy.
// ---------------------------------------------------------------------------
#define ATILE (64 * SKB)             // 9216 bytes: one 64x64 bf16 tile (padded)
#define QTILE (128 * SKB)            // 18432
#define DSMEM_A (2 * QTILE + 8 * ATILE)  // 110592

__global__ __launch_bounds__(256, 1) void attn_mma() {
    extern __shared__ char dsm[];
    const uint32_t sbase = smem_u32(dsm);
    const uint32_t kvbase = sbase + 2 * QTILE;

    const int tid  = threadIdx.x;
    const int lane = tid & 31;
    const int wid  = tid >> 5;
    const int wm   = wid * 16;
    const int bh   = blockIdx.y;
    const int q0   = blockIdx.x * 128;
    const int nt   = 2 * (blockIdx.x + 1);

    // load Q (hi/lo) tiles
    {
        const __nv_bfloat16* qs[2] = {g_qhi, g_qlo};
#pragma unroll
        for (int it = 0; it < 8; it++) {
            const int idx = tid + it * 256;       // 0..2047
            const int half = idx >> 10;
            const int rem = idx & 1023;
            const int row = rem >> 3;
            const int seg = rem & 7;
            cp16(sbase + (uint32_t)half * QTILE + (uint32_t)row * SKB + seg * 16,
                 qs[half] + ((size_t)(bh * T_LEN + q0 + row) * D_HEAD + seg * 8));
        }
        cp_commit();
    }

    const __nv_bfloat16* kvsrc[4] = {g_khi, g_klo, g_vhi, g_vlo};
    auto issue_kv = [&](int j0, int buf) {
#pragma unroll
        for (int it = 0; it < 8; it++) {
            const int idx = tid + it * 256;       // 0..2047
            const int sub = idx >> 9;             // 0..3
            const int rem = idx & 511;
            const int row = rem >> 3;
            const int seg = rem & 7;
            cp16(kvbase + (uint32_t)(buf * 4 + sub) * ATILE + (uint32_t)row * SKB + seg * 16,
                 kvsrc[sub] + ((size_t)(bh * T_LEN + j0 + row) * D_HEAD + seg * 8));
        }
        cp_commit();
    };

    issue_kv(0, 0);

    float o[8][4];
#pragma unroll
    for (int ni = 0; ni < 8; ni++)
#pragma unroll
        for (int e = 0; e < 4; e++) o[ni][e] = 0.f;
    float m0 = -1e30f, m1 = -1e30f, l0 = 0.f, l1 = 0.f;
    uint32_t qh[4][4], ql[4][4];

    const int g  = lane >> 2;
    const int tg = lane & 3;
    const int brow = lane & 7;
    const int bsel = ((lane >> 3) & 1) * 8;

    for (int t = 0; t < nt; t++) {
        const int j0 = t * 64;
        if (t + 1 < nt) { issue_kv((t + 1) * 64, (t + 1) & 1); cp_wait1(); }
        else            { cp_wait0(); }
        __syncthreads();

        if (t == 0) {
            const int arow = lane & 15;
            const int acol = (lane >> 4) << 3;
#pragma unroll
            for (int k16 = 0; k16 < 4; k16++) {
                const uint32_t ad = sbase + (uint32_t)(wm + arow) * SKB
                                  + (uint32_t)(k16 * 16 + acol) * 2;
                ldmat4(qh[k16], ad);
                ldmat4(ql[k16], ad + QTILE);
            }
        }

        const uint32_t kb = kvbase + (uint32_t)((t & 1) * 4) * ATILE;

        // S = Q K^T (bf16x3)
        float s[8][4];
#pragma unroll
        for (int ni = 0; ni < 8; ni++) {
#pragma unroll
            for (int e = 0; e < 4; e++) s[ni][e] = 0.f;
#pragma unroll
            for (int k16 = 0; k16 < 4; k16++) {
                const uint32_t bd = kb + (uint32_t)(ni * 8 + brow) * SKB
                                  + (uint32_t)(k16 * 16 + bsel) * 2;
                uint32_t kh[2], kl[2];
                ldmat2(kh, bd);
                ldmat2(kl, bd + ATILE);
                mma16816(s[ni], qh[k16], kh);
                mma16816(s[ni], qh[k16], kl);
                mma16816(s[ni], ql[k16], kh);
            }
        }

        // causal mask (only last two tiles can straddle the diagonal)
        if (t >= nt - 2) {
            const int r0 = q0 + wm + g;
#pragma unroll
            for (int ni = 0; ni < 8; ni++) {
                const int cbase = j0 + ni * 8 + 2 * tg;
#pragma unroll
                for (int e = 0; e < 4; e++) {
                    const int col = cbase + (e & 1);
                    const int row = (e < 2) ? r0 : r0 + 8;
                    if (col > row) s[ni][e] = -1e30f;
                }
            }
        }

        // online softmax
        float tm0 = -1e30f, tm1 = -1e30f;
#pragma unroll
        for (int ni = 0; ni < 8; ni++) {
            tm0 = fmaxf(tm0, fmaxf(s[ni][0], s[ni][1]));
            tm1 = fmaxf(tm1, fmaxf(s[ni][2], s[ni][3]));
        }
        tm0 = qmax(tm0); tm1 = qmax(tm1);
        const float mn0 = fmaxf(m0, tm0);
        const float mn1 = fmaxf(m1, tm1);
        const float corr0 = __expf(m0 - mn0);
        const float corr1 = __expf(m1 - mn1);
        m0 = mn0; m1 = mn1;

        float ps0 = 0.f, ps1 = 0.f;
#pragma unroll
        for (int ni = 0; ni < 8; ni++) {
            s[ni][0] = __expf(s[ni][0] - m0);
            s[ni][1] = __expf(s[ni][1] - m0);
            s[ni][2] = __expf(s[ni][2] - m1);
            s[ni][3] = __expf(s[ni][3] - m1);
            ps0 += s[ni][0] + s[ni][1];
            ps1 += s[ni][2] + s[ni][3];
        }
        ps0 = qsum(ps0); ps1 = qsum(ps1);
        l0 = l0 * corr0 + ps0;
        l1 = l1 * corr1 + ps1;
#pragma unroll
        for (int ni = 0; ni < 8; ni++) {
            o[ni][0] *= corr0; o[ni][1] *= corr0;
            o[ni][2] *= corr1; o[ni][3] *= corr1;
        }

        // O += P V  (P split hi/lo; V tiles hi/lo in smem, trans ldmatrix)
#pragma unroll
        for (int kj = 0; kj < 4; kj++) {
            uint32_t ah[4], al[4];
#pragma unroll
            for (int half = 0; half < 2; half++) {
                const int sn = 2 * kj + half;
                const float p0 = s[sn][0], p1 = s[sn][1];
                const float p2 = s[sn][2], p3 = s[sn][3];
                ah[2 * half + 0] = packbf(p0, p1);
                ah[2 * half + 1] = packbf(p2, p3);
                al[2 * half + 0] = packbf(p0 - __bfloat162float(__float2bfloat16(p0)),
                                          p1 - __bfloat162float(__float2bfloat16(p1)));
                al[2 * half + 1] = packbf(p2 - __bfloat162float(__float2bfloat16(p2)),
                                          p3 - __bfloat162float(__float2bfloat16(p3)));
            }
            // reorder to A-frag register order {a0,a1,a2,a3}:
            // a0=(g, k0..7)=tile2kj c01, a1=(g+8,k0..7)=tile2kj c23,
            // a2=(g, k8..15)=tile2kj+1 c01, a3=(g+8,k8..15)=tile2kj+1 c23
            uint32_t Ah[4] = {ah[0], ah[1], ah[2], ah[3]};
            uint32_t Al[4] = {al[0], al[1], al[2], al[3]};
            const int vrow = kj * 16 + bsel + brow;
#pragma unroll
            for (int ni = 0; ni < 8; ni++) {
                const uint32_t vd = kb + 2 * ATILE + (uint32_t)vrow * SKB + ni * 16;
                uint32_t vh[2], vl[2];
                ldmat2t(vh, vd);
                ldmat2t(vl, vd + ATILE);
                mma16816(o[ni], Ah, vh);
                mma16816(o[ni], Ah, vl);
                mma16816(o[ni], Al, vh);
            }
        }
        __syncthreads();
    }

    // epilogue: normalize and write bf16 hi/lo of y (B,T,C layout)
    const float inv0 = 1.f / l0;
    const float inv1 = 1.f / l1;
    const int b = bh >> 4;
    const int h = bh & 15;
    const int r0 = q0 + wm + g;
#pragma unroll
    for (int ni = 0; ni < 8; ni++) {
        const int d = ni * 8 + 2 * tg;
#pragma unroll
        for (int rr = 0; rr < 2; rr++) {
            const int row = r0 + rr * 8;
            const float y0 = o[ni][2 * rr + 0] * (rr ? inv1 : inv0);
            const float y1 = o[ni][2 * rr + 1] * (rr ? inv1 : inv0);
            const size_t off = (size_t)(b * T_LEN + row) * C_DIM + h * D_HEAD + d;
            *(uint32_t*)(g_yhi + off) = packbf(y0, y1);
            *(uint32_t*)(g_ylo + off) =
                packbf(y0 - __bfloat162float(__float2bfloat16(y0)),
                       y1 - __bfloat162float(__float2bfloat16(y1)));
        }
    }
}

// ---------------------------------------------------------------------------
extern "C" void kernel_launch(void* const* d_in, const int* in_sizes, int n_in,
                              void* d_out, int out_size) {
    const float* x  = (const float*)d_in[0];   // (8,1024,1024)
    const float* Wa = (const float*)d_in[1];   // (3072,1024)
    const float* Wp = (const float*)d_in[2];   // (1024,1024)
    float* out = (float*)d_out;                // (8,1024,1024)

    cudaFuncSetAttribute(gemm_mma<0>, cudaFuncAttributeMaxDynamicSharedMemorySize, DSMEM);
    cudaFuncSetAttribute(gemm_mma<1>, cudaFuncAttributeMaxDynamicSharedMemorySize, DSMEM);
    cudaFuncSetAttribute(attn_mma, cudaFuncAttributeMaxDynamicSharedMemorySize, DSMEM_A);

    __nv_bfloat16 *xhi, *xlo, *wahi, *walo, *wphi, *wplo, *yhi, *ylo;
    cudaGetSymbolAddress((void**)&xhi,  g_xhi);
    cudaGetSymbolAddress((void**)&xlo,  g_xlo);
    cudaGetSymbolAddress((void**)&wahi, g_wahi);
    cudaGetSymbolAddress((void**)&walo, g_walo);
    cudaGetSymbolAddress((void**)&wphi, g_wphi);
    cudaGetSymbolAddress((void**)&wplo, g_wplo);
    cudaGetSymbolAddress((void**)&yhi,  g_yhi);
    cudaGetSymbolAddress((void**)&ylo,  g_ylo);

    // 1) fp32 -> bf16 hi/lo splits of inputs
    split_kernel<<<(M_ROWS * K_DIM / 4) / 256, 256>>>(x,  xhi,  xlo,  M_ROWS * K_DIM / 4);
    split_kernel<<<(3 * C_DIM * K_DIM / 4) / 256, 256>>>(Wa, wahi, walo, 3 * C_DIM * K_DIM / 4);
    split_kernel<<<(C_DIM * K_DIM / 4) / 256, 256>>>(Wp, wphi, wplo, C_DIM * K_DIM / 4);

    // 2) QKV GEMM: q,k -> fp32 head layout; v -> bf16 hi/lo head layout
    gemm_mma<0><<<dim3(3072 / 128, M_ROWS / 128), 256, DSMEM>>>(xhi, xlo, wahi, walo, nullptr);

    // 3) Rotary: fp32 q,k -> rotated bf16 hi/lo q,k
    rotary_kernel<<<(BH * T_LEN) / 256, 256>>>();

    // 4) Tensor-core causal flash attention -> y bf16 hi/lo
    attn_mma<<<dim3(T_LEN / 128, BH), 256, DSMEM_A>>>();

    // 5) Projection GEMM
    gemm_mma<1><<<dim3(1024 / 128, M_ROWS / 128), 256, DSMEM>>>(yhi, ylo, wphi, wplo, out);
}

// round 6
// speedup vs baseline: 3.5426x; 1.0057x over previous
#include <cuda_runtime.h>
#include <cuda_bf16.h>
#include <math.h>
#include <stdint.h>

// Problem constants
#define B_SZ   8
#define T_LEN  1024
#define C_DIM  1024
#define H_NUM  16
#define D_HEAD 64
#define BH     (B_SZ * H_NUM)        // 128
#define M_ROWS (B_SZ * T_LEN)        // 8192
#define K_DIM  1024

// fp32 scratch (pre-rotary q/k only)
__device__ float g_q[BH * T_LEN * D_HEAD];
__device__ float g_k[BH * T_LEN * D_HEAD];

// bf16 hi/lo split buffers
__device__ __nv_bfloat16 g_xhi[M_ROWS * K_DIM];
__device__ __nv_bfloat16 g_xlo[M_ROWS * K_DIM];
__device__ __nv_bfloat16 g_wahi[3 * C_DIM * K_DIM];
__device__ __nv_bfloat16 g_walo[3 * C_DIM * K_DIM];
__device__ __nv_bfloat16 g_wphi[C_DIM * K_DIM];
__device__ __nv_bfloat16 g_wplo[C_DIM * K_DIM];
__device__ __nv_bfloat16 g_qhi[BH * T_LEN * D_HEAD];
__device__ __nv_bfloat16 g_qlo[BH * T_LEN * D_HEAD];
__device__ __nv_bfloat16 g_khi[BH * T_LEN * D_HEAD];
__device__ __nv_bfloat16 g_klo[BH * T_LEN * D_HEAD];
__device__ __nv_bfloat16 g_vhi[BH * T_LEN * D_HEAD];
__device__ __nv_bfloat16 g_vlo[BH * T_LEN * D_HEAD];
__device__ __nv_bfloat16 g_yhi[M_ROWS * C_DIM];
__device__ __nv_bfloat16 g_ylo[M_ROWS * C_DIM];

// ---------------------------------------------------------------------------
// helpers
// ---------------------------------------------------------------------------
__device__ __forceinline__ uint32_t smem_u32(const void* p) {
    uint32_t a;
    asm("{ .reg .u64 t; cvta.to.shared.u64 t, %1; cvt.u32.u64 %0, t; }"
        : "=r"(a) : "l"(p));
    return a;
}
__device__ __forceinline__ void cp16(uint32_t dst, const void* src) {
    asm volatile("cp.async.cg.shared.global [%0], [%1], 16;" :: "r"(dst), "l"(src));
}
__device__ __forceinline__ void cp_commit() {
    asm volatile("cp.async.commit_group;" ::: "memory");
}
__device__ __forceinline__ void cp_wait1() {
    asm volatile("cp.async.wait_group 1;" ::: "memory");
}
__device__ __forceinline__ void cp_wait0() {
    asm volatile("cp.async.wait_group 0;" ::: "memory");
}
__device__ __forceinline__ void ldmat4(uint32_t* r, uint32_t addr) {
    asm volatile("ldmatrix.sync.aligned.m8n8.x4.shared.b16 {%0,%1,%2,%3}, [%4];"
                 : "=r"(r[0]), "=r"(r[1]), "=r"(r[2]), "=r"(r[3]) : "r"(addr));
}
__device__ __forceinline__ void ldmat2(uint32_t* r, uint32_t addr) {
    asm volatile("ldmatrix.sync.aligned.m8n8.x2.shared.b16 {%0,%1}, [%2];"
                 : "=r"(r[0]), "=r"(r[1]) : "r"(addr));
}
__device__ __forceinline__ void ldmat2t(uint32_t* r, uint32_t addr) {
    asm volatile("ldmatrix.sync.aligned.m8n8.x2.trans.shared.b16 {%0,%1}, [%2];"
                 : "=r"(r[0]), "=r"(r[1]) : "r"(addr));
}
__device__ __forceinline__ void mma16816(float* c, const uint32_t* a, const uint32_t* b) {
    asm volatile(
        "mma.sync.aligned.m16n8k16.row.col.f32.bf16.bf16.f32 "
        "{%0,%1,%2,%3}, {%4,%5,%6,%7}, {%8,%9}, {%0,%1,%2,%3};"
        : "+f"(c[0]), "+f"(c[1]), "+f"(c[2]), "+f"(c[3])
        : "r"(a[0]), "r"(a[1]), "r"(a[2]), "r"(a[3]), "r"(b[0]), "r"(b[1]));
}
__device__ __forceinline__ uint32_t packbf(float a, float b) {
    uint32_t r;
    asm("cvt.rn.bf16x2.f32 %0, %1, %2;" : "=r"(r) : "f"(b), "f"(a));
    return r;
}
__device__ __forceinline__ float qmax(float x) {
    x = fmaxf(x, __shfl_xor_sync(0xffffffffu, x, 1));
    x = fmaxf(x, __shfl_xor_sync(0xffffffffu, x, 2));
    return x;
}
__device__ __forceinline__ float qsum(float x) {
    x += __shfl_xor_sync(0xffffffffu, x, 1);
    x += __shfl_xor_sync(0xffffffffu, x, 2);
    return x;
}

// ---------------------------------------------------------------------------
// fp32 -> (bf16 hi, bf16 lo) split
// ---------------------------------------------------------------------------
__global__ __launch_bounds__(256) void split_kernel(const float* __restrict__ src,
                                                    __nv_bfloat16* __restrict__ hi,
                                                    __nv_bfloat16* __restrict__ lo,
                                                    int n4) {
    int i = blockIdx.x * blockDim.x + threadIdx.x;
    if (i >= n4) return;
    float4 x = ((const float4*)src)[i];
    float xs[4] = {x.x, x.y, x.z, x.w};
    __nv_bfloat16 h[4], l[4];
#pragma unroll
    for (int e = 0; e < 4; e++) {
        h[e] = __float2bfloat16(xs[e]);
        l[e] = __float2bfloat16(xs[e] - __bfloat162float(h[e]));
    }
    ((uint2*)hi)[i] = *(uint2*)h;
    ((uint2*)lo)[i] = *(uint2*)l;
}

// ---------------------------------------------------------------------------
// mma.sync bf16x3 GEMM, interleaved fragment loads + single sync per chunk
// ---------------------------------------------------------------------------
#define SKE 72
#define SKB (SKE * 2)                // 144 bytes
#define TILE_B (128 * SKB)           // 18432
#define DSMEM (2 * 4 * TILE_B)       // 147456

template <int MODE>
__global__ __launch_bounds__(256, 1) void gemm_mma(
    const __nv_bfloat16* __restrict__ Ahi, const __nv_bfloat16* __restrict__ Alo,
    const __nv_bfloat16* __restrict__ Bhi, const __nv_bfloat16* __restrict__ Blo,
    float* __restrict__ Cout) {
    extern __shared__ char dsm[];
    const uint32_t sbase = smem_u32(dsm);

    const int tid  = threadIdx.x;
    const int lane = tid & 31;
    const int wid  = tid >> 5;
    const int wm   = (wid & 1) * 64;
    const int wn   = (wid >> 1) * 32;
    const int bn   = blockIdx.x * 128;
    const int bm   = blockIdx.y * 128;

    float c[4][4][4];
#pragma unroll
    for (int mi = 0; mi < 4; mi++)
#pragma unroll
        for (int ni = 0; ni < 4; ni++)
#pragma unroll
            for (int e = 0; e < 4; e++) c[mi][ni][e] = 0.f;

    const __nv_bfloat16* srcs[4] = {Ahi, Alo, Bhi, Blo};
    const int gbase[2] = {bm, bn};

    auto issue = [&](int ch, int buf) {
        const int k0 = ch * 64;
#pragma unroll
        for (int t = 0; t < 4; t++) {
            const __nv_bfloat16* src = srcs[t];
            const int gb = gbase[t >> 1];
            const uint32_t dbase = sbase + (uint32_t)(buf * 4 + t) * TILE_B;
#pragma unroll
            for (int it = 0; it < 4; it++) {
                const int idx = tid + it * 256;
                const int row = idx >> 3;
                const int seg = idx & 7;
                cp16(dbase + (uint32_t)row * SKB + seg * 16,
                     src + (size_t)(gb + row) * K_DIM + k0 + seg * 8);
            }
        }
        cp_commit();
    };

    issue(0, 0);

    const int arow = lane & 15;
    const int acol = (lane >> 4) << 3;
    const int brow = lane & 7;
    const int bcol = ((lane >> 3) & 1) << 3;

    for (int ch = 0; ch < 16; ch++) {
        cp_wait0();
        __syncthreads();
        // all fragment reads of the previous chunk are complete at this point,
        // so it is safe to start overwriting the other buffer.
        if (ch < 15) issue(ch + 1, (ch + 1) & 1);

        const uint32_t abase = sbase + (uint32_t)((ch & 1) * 4 + 0) * TILE_B;
        const uint32_t bbase = sbase + (uint32_t)((ch & 1) * 4 + 2) * TILE_B;

#pragma unroll
        for (int k16 = 0; k16 < 4; k16++) {
            uint32_t ah[4][4], al[4][4];
#pragma unroll
            for (int mi = 0; mi < 4; mi++) {
                const uint32_t ad = abase + (uint32_t)(wm + mi * 16 + arow) * SKB
                                  + (uint32_t)(k16 * 16 + acol) * 2;
                ldmat4(ah[mi], ad);
                ldmat4(al[mi], ad + TILE_B);
            }
#pragma unroll
            for (int ni = 0; ni < 4; ni++) {
                uint32_t bh[2], bl[2];
                const uint32_t bd = bbase + (uint32_t)(wn + ni * 8 + brow) * SKB
                                  + (uint32_t)(k16 * 16 + bcol) * 2;
                ldmat2(bh, bd);
                ldmat2(bl, bd + TILE_B);
#pragma unroll
                for (int mi = 0; mi < 4; mi++) {
                    mma16816(c[mi][ni], ah[mi], bh);
                    mma16816(c[mi][ni], ah[mi], bl);
                    mma16816(c[mi][ni], al[mi], bh);
                }
            }
        }
    }

    const int g  = lane >> 2;
    const int tg = lane & 3;
#pragma unroll
    for (int mi = 0; mi < 4; mi++) {
#pragma unroll
        for (int ni = 0; ni < 4; ni++) {
            const int n = bn + wn + ni * 8 + 2 * tg;
            const int m0r = bm + wm + mi * 16 + g;
            if (MODE == 0) {
                const int part = n >> 10;
                const int cc = n & 1023;
                const int h = cc >> 6;
                const int d = cc & 63;
#pragma unroll
                for (int rr = 0; rr < 2; rr++) {
                    const int m = m0r + rr * 8;
                    const int b = m >> 10;
                    const int t = m & 1023;
                    const size_t off = ((size_t)(b * 16 + h) * T_LEN + t) * D_HEAD + d;
                    float2 v = rr ? make_float2(c[mi][ni][2], c[mi][ni][3])
                                  : make_float2(c[mi][ni][0], c[mi][ni][1]);
                    if (part == 0)      *(float2*)(g_q + off) = v;
                    else if (part == 1) *(float2*)(g_k + off) = v;
                    else {
                        uint32_t hi = packbf(v.x, v.y);
                        float hx = __bfloat162float(__float2bfloat16(v.x));
                        float hy = __bfloat162float(__float2bfloat16(v.y));
                        uint32_t lo = packbf(v.x - hx, v.y - hy);
                        *(uint32_t*)(g_vhi + off) = hi;
                        *(uint32_t*)(g_vlo + off) = lo;
                    }
                }
            } else {
                *(float2*)(Cout + (size_t)m0r * C_DIM + n) =
                    make_float2(c[mi][ni][0], c[mi][ni][1]);
                *(float2*)(Cout + (size_t)(m0r + 8) * C_DIM + n) =
                    make_float2(c[mi][ni][2], c[mi][ni][3]);
            }
        }
    }
}

// ---------------------------------------------------------------------------
// Rotary: fast __sincosf (|q| small, abs err ~1e-6 — fine for 1e-3 budget)
// ---------------------------------------------------------------------------
__global__ __launch_bounds__(256) void rotary_kernel() {
    const int idx = blockIdx.x * blockDim.x + threadIdx.x;
    if (idx >= BH * T_LEN) return;
    const float* qp = g_q + (size_t)idx * D_HEAD;
    const float* kp = g_k + (size_t)idx * D_HEAD;

    float q[64], k[64];
#pragma unroll
    for (int i = 0; i < 16; i++) {
        ((float4*)q)[i] = ((const float4*)qp)[i];
        ((float4*)k)[i] = ((const float4*)kp)[i];
    }
    uint32_t* qh32 = (uint32_t*)g_qhi + (size_t)idx * 32;
    uint32_t* ql32 = (uint32_t*)g_qlo + (size_t)idx * 32;
    uint32_t* kh32 = (uint32_t*)g_khi + (size_t)idx * 32;
    uint32_t* kl32 = (uint32_t*)g_klo + (size_t)idx * 32;

#pragma unroll
    for (int i = 0; i < 32; i++) {
        float qo[2], ko[2];
#pragma unroll
        for (int e = 0; e < 2; e++) {
            const int d = 2 * i + e;
            float cc, sn;
            __sincosf(q[d], &sn, &cc);
            const float rq = (d < 32) ? -q[2 * d + 1] : q[2 * d - 64];
            const float rk = (d < 32) ? -k[2 * d + 1] : k[2 * d - 64];
            qo[e] = q[d] * cc + rq * sn;
            ko[e] = k[d] * cc + rk * sn;
        }
        qh32[i] = packbf(qo[0], qo[1]);
        ql32[i] = packbf(qo[0] - __bfloat162float(__float2bfloat16(qo[0])),
                         qo[1] - __bfloat162float(__float2bfloat16(qo[1])));
        kh32[i] = packbf(ko[0], ko[1]);
        kl32[i] = packbf(ko[0] - __bfloat162float(__float2bfloat16(ko[0])),
                         ko[1] - __bfloat162float(__float2bfloat16(ko[1])));
    }
}

// ---------------------------------------------------------------------------
// Tensor-core flash attention (causal, scale=1.0). As round 5 (verified).
// ---------------------------------------------------------------------------
#define ATILE (64 * SKB)             // 9216
#define QTILE (128 * SKB)            // 18432
#define DSMEM_A (2 * QTILE + 8 * ATILE)  // 110592

__global__ __launch_bounds__(256, 1) void attn_mma() {
    extern __shared__ char dsm[];
    const uint32_t sbase = smem_u32(dsm);
    const uint32_t kvbase = sbase + 2 * QTILE;

    const int tid  = threadIdx.x;
    const int lane = tid & 31;
    const int wid  = tid >> 5;
    const int wm   = wid * 16;
    const int bh   = blockIdx.y;
    const int q0   = blockIdx.x * 128;
    const int nt   = 2 * (blockIdx.x + 1);

    {
        const __nv_bfloat16* qs[2] = {g_qhi, g_qlo};
#pragma unroll
        for (int it = 0; it < 8; it++) {
            const int idx = tid + it * 256;
            const int half = idx >> 10;
            const int rem = idx & 1023;
            const int row = rem >> 3;
            const int seg = rem & 7;
            cp16(sbase + (uint32_t)half * QTILE + (uint32_t)row * SKB + seg * 16,
                 qs[half] + ((size_t)(bh * T_LEN + q0 + row) * D_HEAD + seg * 8));
        }
        cp_commit();
    }

    const __nv_bfloat16* kvsrc[4] = {g_khi, g_klo, g_vhi, g_vlo};
    auto issue_kv = [&](int j0, int buf) {
#pragma unroll
        for (int it = 0; it < 8; it++) {
            const int idx = tid + it * 256;
            const int sub = idx >> 9;
            const int rem = idx & 511;
            const int row = rem >> 3;
            const int seg = rem & 7;
            cp16(kvbase + (uint32_t)(buf * 4 + sub) * ATILE + (uint32_t)row * SKB + seg * 16,
                 kvsrc[sub] + ((size_t)(bh * T_LEN + j0 + row) * D_HEAD + seg * 8));
        }
        cp_commit();
    };

    issue_kv(0, 0);

    float o[8][4];
#pragma unroll
    for (int ni = 0; ni < 8; ni++)
#pragma unroll
        for (int e = 0; e < 4; e++) o[ni][e] = 0.f;
    float m0 = -1e30f, m1 = -1e30f, l0 = 0.f, l1 = 0.f;
    uint32_t qh[4][4], ql[4][4];

    const int g  = lane >> 2;
    const int tg = lane & 3;
    const int brow = lane & 7;
    const int bsel = ((lane >> 3) & 1) * 8;

    for (int t = 0; t < nt; t++) {
        const int j0 = t * 64;
        if (t + 1 < nt) { issue_kv((t + 1) * 64, (t + 1) & 1); cp_wait1(); }
        else            { cp_wait0(); }
        __syncthreads();

        if (t == 0) {
            const int arow = lane & 15;
            const int acol = (lane >> 4) << 3;
#pragma unroll
            for (int k16 = 0; k16 < 4; k16++) {
                const uint32_t ad = sbase + (uint32_t)(wm + arow) * SKB
                                  + (uint32_t)(k16 * 16 + acol) * 2;
                ldmat4(qh[k16], ad);
                ldmat4(ql[k16], ad + QTILE);
            }
        }

        const uint32_t kb = kvbase + (uint32_t)((t & 1) * 4) * ATILE;

        float s[8][4];
#pragma unroll
        for (int ni = 0; ni < 8; ni++) {
#pragma unroll
            for (int e = 0; e < 4; e++) s[ni][e] = 0.f;
#pragma unroll
            for (int k16 = 0; k16 < 4; k16++) {
                const uint32_t bd = kb + (uint32_t)(ni * 8 + brow) * SKB
                                  + (uint32_t)(k16 * 16 + bsel) * 2;
                uint32_t kh[2], kl[2];
                ldmat2(kh, bd);
                ldmat2(kl, bd + ATILE);
                mma16816(s[ni], qh[k16], kh);
                mma16816(s[ni], qh[k16], kl);
                mma16816(s[ni], ql[k16], kh);
            }
        }

        if (t >= nt - 2) {
            const int r0 = q0 + wm + g;
#pragma unroll
            for (int ni = 0; ni < 8; ni++) {
                const int cbase = j0 + ni * 8 + 2 * tg;
#pragma unroll
                for (int e = 0; e < 4; e++) {
                    const int col = cbase + (e & 1);
                    const int row = (e < 2) ? r0 : r0 + 8;
                    if (col > row) s[ni][e] = -1e30f;
                }
            }
        }

        float tm0 = -1e30f, tm1 = -1e30f;
#pragma unroll
        for (int ni = 0; ni < 8; ni++) {
            tm0 = fmaxf(tm0, fmaxf(s[ni][0], s[ni][1]));
            tm1 = fmaxf(tm1, fmaxf(s[ni][2], s[ni][3]));
        }
        tm0 = qmax(tm0); tm1 = qmax(tm1);
        const float mn0 = fmaxf(m0, tm0);
        const float mn1 = fmaxf(m1, tm1);
        const float corr0 = __expf(m0 - mn0);
        const float corr1 = __expf(m1 - mn1);
        m0 = mn0; m1 = mn1;

        float ps0 = 0.f, ps1 = 0.f;
#pragma unroll
        for (int ni = 0; ni < 8; ni++) {
            s[ni][0] = __expf(s[ni][0] - m0);
            s[ni][1] = __expf(s[ni][1] - m0);
            s[ni][2] = __expf(s[ni][2] - m1);
            s[ni][3] = __expf(s[ni][3] - m1);
            ps0 += s[ni][0] + s[ni][1];
            ps1 += s[ni][2] + s[ni][3];
        }
        ps0 = qsum(ps0); ps1 = qsum(ps1);
        l0 = l0 * corr0 + ps0;
        l1 = l1 * corr1 + ps1;
#pragma unroll
        for (int ni = 0; ni < 8; ni++) {
            o[ni][0] *= corr0; o[ni][1] *= corr0;
            o[ni][2] *= corr1; o[ni][3] *= corr1;
        }

#pragma unroll
        for (int kj = 0; kj < 4; kj++) {
            uint32_t Ah[4], Al[4];
#pragma unroll
            for (int half = 0; half < 2; half++) {
                const int sn = 2 * kj + half;
                const float p0 = s[sn][0], p1 = s[sn][1];
                const float p2 = s[sn][2], p3 = s[sn][3];
                Ah[2 * half + 0] = packbf(p0, p1);
                Ah[2 * half + 1] = packbf(p2, p3);
                Al[2 * half + 0] = packbf(p0 - __bfloat162float(__float2bfloat16(p0)),
                                          p1 - __bfloat162float(__float2bfloat16(p1)));
                Al[2 * half + 1] = packbf(p2 - __bfloat162float(__float2bfloat16(p2)),
                                          p3 - __bfloat162float(__float2bfloat16(p3)));
            }
            const int vrow = kj * 16 + bsel + brow;
#pragma unroll
            for (int ni = 0; ni < 8; ni++) {
                const uint32_t vd = kb + 2 * ATILE + (uint32_t)vrow * SKB + ni * 16;
                uint32_t vh[2], vl[2];
                ldmat2t(vh, vd);
                ldmat2t(vl, vd + ATILE);
                mma16816(o[ni], Ah, vh);
                mma16816(o[ni], Ah, vl);
                mma16816(o[ni], Al, vh);
            }
        }
        __syncthreads();
    }

    const float inv0 = 1.f / l0;
    const float inv1 = 1.f / l1;
    const int b = bh >> 4;
    const int h = bh & 15;
    const int r0 = q0 + wm + g;
#pragma unroll
    for (int ni = 0; ni < 8; ni++) {
        const int d = ni * 8 + 2 * tg;
#pragma unroll
        for (int rr = 0; rr < 2; rr++) {
            const int row = r0 + rr * 8;
            const float y0 = o[ni][2 * rr + 0] * (rr ? inv1 : inv0);
            const float y1 = o[ni][2 * rr + 1] * (rr ? inv1 : inv0);
            const size_t off = (size_t)(b * T_LEN + row) * C_DIM + h * D_HEAD + d;
            *(uint32_t*)(g_yhi + off) = packbf(y0, y1);
            *(uint32_t*)(g_ylo + off) =
                packbf(y0 - __bfloat162float(__float2bfloat16(y0)),
                       y1 - __bfloat162float(__float2bfloat16(y1)));
        }
    }
}

// ---------------------------------------------------------------------------
extern "C" void kernel_launch(void* const* d_in, const int* in_sizes, int n_in,
                              void* d_out, int out_size) {
    const float* x  = (const float*)d_in[0];   // (8,1024,1024)
    const float* Wa = (const float*)d_in[1];   // (3072,1024)
    const float* Wp = (const float*)d_in[2];   // (1024,1024)
    float* out = (float*)d_out;                // (8,1024,1024)

    cudaFuncSetAttribute(gemm_mma<0>, cudaFuncAttributeMaxDynamicSharedMemorySize, DSMEM);
    cudaFuncSetAttribute(gemm_mma<1>, cudaFuncAttributeMaxDynamicSharedMemorySize, DSMEM);
    cudaFuncSetAttribute(attn_mma, cudaFuncAttributeMaxDynamicSharedMemorySize, DSMEM_A);

    __nv_bfloat16 *xhi, *xlo, *wahi, *walo, *wphi, *wplo, *yhi, *ylo;
    cudaGetSymbolAddress((void**)&xhi,  g_xhi);
    cudaGetSymbolAddress((void**)&xlo,  g_xlo);
    cudaGetSymbolAddress((void**)&wahi, g_wahi);
    cudaGetSymbolAddress((void**)&walo, g_walo);
    cudaGetSymbolAddress((void**)&wphi, g_wphi);
    cudaGetSymbolAddress((void**)&wplo, g_wplo);
    cudaGetSymbolAddress((void**)&yhi,  g_yhi);
    cudaGetSymbolAddress((void**)&ylo,  g_ylo);

    split_kernel<<<(M_ROWS * K_DIM / 4) / 256, 256>>>(x,  xhi,  xlo,  M_ROWS * K_DIM / 4);
    split_kernel<<<(3 * C_DIM * K_DIM / 4) / 256, 256>>>(Wa, wahi, walo, 3 * C_DIM * K_DIM / 4);
    split_kernel<<<(C_DIM * K_DIM / 4) / 256, 256>>>(Wp, wphi, wplo, C_DIM * K_DIM / 4);

    gemm_mma<0><<<dim3(3072 / 128, M_ROWS / 128), 256, DSMEM>>>(xhi, xlo, wahi, walo, nullptr);

    rotary_kernel<<<(BH * T_LEN) / 256, 256>>>();

    attn_mma<<<dim3(T_LEN / 128, BH), 256, DSMEM_A>>>();

    gemm_mma<1><<<dim3(1024 / 128, M_ROWS / 128), 256, DSMEM>>>(yhi, ylo, wphi, wplo, out);
}

// round 7
// speedup vs baseline: 3.6252x; 1.0233x over previous
#include <cuda_runtime.h>
#include <cuda_bf16.h>
#include <math.h>
#include <stdint.h>

// Problem constants
#define B_SZ   8
#define T_LEN  1024
#define C_DIM  1024
#define H_NUM  16
#define D_HEAD 64
#define BH     (B_SZ * H_NUM)        // 128
#define M_ROWS (B_SZ * T_LEN)        // 8192
#define K_DIM  1024

// fp32 scratch (pre-rotary q/k only)
__device__ float g_q[BH * T_LEN * D_HEAD];
__device__ float g_k[BH * T_LEN * D_HEAD];

// bf16 hi/lo split buffers
__device__ __nv_bfloat16 g_xhi[M_ROWS * K_DIM];
__device__ __nv_bfloat16 g_xlo[M_ROWS * K_DIM];
__device__ __nv_bfloat16 g_wahi[3 * C_DIM * K_DIM];
__device__ __nv_bfloat16 g_walo[3 * C_DIM * K_DIM];
__device__ __nv_bfloat16 g_wphi[C_DIM * K_DIM];
__device__ __nv_bfloat16 g_wplo[C_DIM * K_DIM];
__device__ __nv_bfloat16 g_qhi[BH * T_LEN * D_HEAD];
__device__ __nv_bfloat16 g_qlo[BH * T_LEN * D_HEAD];
__device__ __nv_bfloat16 g_khi[BH * T_LEN * D_HEAD];
__device__ __nv_bfloat16 g_klo[BH * T_LEN * D_HEAD];
__device__ __nv_bfloat16 g_vhi[BH * T_LEN * D_HEAD];
__device__ __nv_bfloat16 g_vlo[BH * T_LEN * D_HEAD];
__device__ __nv_bfloat16 g_yhi[M_ROWS * C_DIM];
__device__ __nv_bfloat16 g_ylo[M_ROWS * C_DIM];

// ---------------------------------------------------------------------------
// helpers
// ---------------------------------------------------------------------------
__device__ __forceinline__ uint32_t smem_u32(const void* p) {
    uint32_t a;
    asm("{ .reg .u64 t; cvta.to.shared.u64 t, %1; cvt.u32.u64 %0, t; }"
        : "=r"(a) : "l"(p));
    return a;
}
__device__ __forceinline__ void cp16(uint32_t dst, const void* src) {
    asm volatile("cp.async.cg.shared.global [%0], [%1], 16;" :: "r"(dst), "l"(src));
}
__device__ __forceinline__ void cp_commit() {
    asm volatile("cp.async.commit_group;" ::: "memory");
}
__device__ __forceinline__ void cp_wait1() {
    asm volatile("cp.async.wait_group 1;" ::: "memory");
}
__device__ __forceinline__ void cp_wait0() {
    asm volatile("cp.async.wait_group 0;" ::: "memory");
}
__device__ __forceinline__ void ldmat4(uint32_t* r, uint32_t addr) {
    asm volatile("ldmatrix.sync.aligned.m8n8.x4.shared.b16 {%0,%1,%2,%3}, [%4];"
                 : "=r"(r[0]), "=r"(r[1]), "=r"(r[2]), "=r"(r[3]) : "r"(addr));
}
__device__ __forceinline__ void ldmat2(uint32_t* r, uint32_t addr) {
    asm volatile("ldmatrix.sync.aligned.m8n8.x2.shared.b16 {%0,%1}, [%2];"
                 : "=r"(r[0]), "=r"(r[1]) : "r"(addr));
}
__device__ __forceinline__ void ldmat2t(uint32_t* r, uint32_t addr) {
    asm volatile("ldmatrix.sync.aligned.m8n8.x2.trans.shared.b16 {%0,%1}, [%2];"
                 : "=r"(r[0]), "=r"(r[1]) : "r"(addr));
}
__device__ __forceinline__ void mma16816(float* c, const uint32_t* a, const uint32_t* b) {
    asm volatile(
        "mma.sync.aligned.m16n8k16.row.col.f32.bf16.bf16.f32 "
        "{%0,%1,%2,%3}, {%4,%5,%6,%7}, {%8,%9}, {%0,%1,%2,%3};"
        : "+f"(c[0]), "+f"(c[1]), "+f"(c[2]), "+f"(c[3])
        : "r"(a[0]), "r"(a[1]), "r"(a[2]), "r"(a[3]), "r"(b[0]), "r"(b[1]));
}
__device__ __forceinline__ uint32_t packbf(float a, float b) {
    uint32_t r;
    asm("cvt.rn.bf16x2.f32 %0, %1, %2;" : "=r"(r) : "f"(b), "f"(a));
    return r;
}
__device__ __forceinline__ float qmax(float x) {
    x = fmaxf(x, __shfl_xor_sync(0xffffffffu, x, 1));
    x = fmaxf(x, __shfl_xor_sync(0xffffffffu, x, 2));
    return x;
}
__device__ __forceinline__ float qsum(float x) {
    x += __shfl_xor_sync(0xffffffffu, x, 1);
    x += __shfl_xor_sync(0xffffffffu, x, 2);
    return x;
}

// ---------------------------------------------------------------------------
// fp32 -> (bf16 hi, bf16 lo) split
// ---------------------------------------------------------------------------
__global__ __launch_bounds__(256) void split_kernel(const float* __restrict__ src,
                                                    __nv_bfloat16* __restrict__ hi,
                                                    __nv_bfloat16* __restrict__ lo,
                                                    int n4) {
    int i = blockIdx.x * blockDim.x + threadIdx.x;
    if (i >= n4) return;
    float4 x = ((const float4*)src)[i];
    float xs[4] = {x.x, x.y, x.z, x.w};
    __nv_bfloat16 h[4], l[4];
#pragma unroll
    for (int e = 0; e < 4; e++) {
        h[e] = __float2bfloat16(xs[e]);
        l[e] = __float2bfloat16(xs[e] - __bfloat162float(h[e]));
    }
    ((uint2*)hi)[i] = *(uint2*)h;
    ((uint2*)lo)[i] = *(uint2*)l;
}

// ---------------------------------------------------------------------------
// mma.sync bf16x3 GEMM: BK=32, 80KB smem -> 2 CTAs/SM for latency hiding.
// 128x128 tile, 256 thr = 8 warps (64x32 microtile each).
// ---------------------------------------------------------------------------
#define GSKE 40
#define GSKB (GSKE * 2)              // 80 bytes/row
#define GTILE (128 * GSKB)           // 10240 bytes: 128 x 32 bf16 tile
#define DSMEM (2 * 4 * GTILE)        // 81920 -> 2 CTAs/SM

template <int MODE>
__global__ __launch_bounds__(256, 2) void gemm_mma(
    const __nv_bfloat16* __restrict__ Ahi, const __nv_bfloat16* __restrict__ Alo,
    const __nv_bfloat16* __restrict__ Bhi, const __nv_bfloat16* __restrict__ Blo,
    float* __restrict__ Cout) {
    extern __shared__ char dsm[];
    const uint32_t sbase = smem_u32(dsm);

    const int tid  = threadIdx.x;
    const int lane = tid & 31;
    const int wid  = tid >> 5;
    const int wm   = (wid & 1) * 64;
    const int wn   = (wid >> 1) * 32;
    const int bn   = blockIdx.x * 128;
    const int bm   = blockIdx.y * 128;

    float c[4][4][4];
#pragma unroll
    for (int mi = 0; mi < 4; mi++)
#pragma unroll
        for (int ni = 0; ni < 4; ni++)
#pragma unroll
            for (int e = 0; e < 4; e++) c[mi][ni][e] = 0.f;

    const __nv_bfloat16* srcs[4] = {Ahi, Alo, Bhi, Blo};
    const int gbase[2] = {bm, bn};

    // one K-chunk = 4 tiles of 128 rows x 32 bf16 (64B/row, 4 x 16B segs)
    auto issue = [&](int ch, int buf) {
        const int k0 = ch * 32;
#pragma unroll
        for (int t = 0; t < 4; t++) {
            const __nv_bfloat16* src = srcs[t];
            const int gb = gbase[t >> 1];
            const uint32_t dbase = sbase + (uint32_t)(buf * 4 + t) * GTILE;
#pragma unroll
            for (int it = 0; it < 2; it++) {
                const int idx = tid + it * 256;     // 0..511
                const int row = idx >> 2;           // 0..127
                const int seg = idx & 3;            // 16B segment
                cp16(dbase + (uint32_t)row * GSKB + seg * 16,
                     src + (size_t)(gb + row) * K_DIM + k0 + seg * 8);
            }
        }
        cp_commit();
    };

    issue(0, 0);

    const int arow = lane & 15;
    const int acol = (lane >> 4) << 3;
    const int brow = lane & 7;
    const int bcol = ((lane >> 3) & 1) << 3;

    for (int ch = 0; ch < 32; ch++) {
        cp_wait0();
        __syncthreads();
        if (ch < 31) issue(ch + 1, (ch + 1) & 1);

        const uint32_t abase = sbase + (uint32_t)((ch & 1) * 4 + 0) * GTILE;
        const uint32_t bbase = sbase + (uint32_t)((ch & 1) * 4 + 2) * GTILE;

#pragma unroll
        for (int k16 = 0; k16 < 2; k16++) {
            // load all B fragments first (16 regs live), then stream A per mi
            uint32_t bh[4][2], bl[4][2];
#pragma unroll
            for (int ni = 0; ni < 4; ni++) {
                const uint32_t bd = bbase + (uint32_t)(wn + ni * 8 + brow) * GSKB
                                  + (uint32_t)(k16 * 16 + bcol) * 2;
                ldmat2(bh[ni], bd);
                ldmat2(bl[ni], bd + GTILE);
            }
#pragma unroll
            for (int mi = 0; mi < 4; mi++) {
                uint32_t ah[4], al[4];
                const uint32_t ad = abase + (uint32_t)(wm + mi * 16 + arow) * GSKB
                                  + (uint32_t)(k16 * 16 + acol) * 2;
                ldmat4(ah, ad);
                ldmat4(al, ad + GTILE);
#pragma unroll
                for (int ni = 0; ni < 4; ni++) {
                    mma16816(c[mi][ni], ah, bh[ni]);
                    mma16816(c[mi][ni], ah, bl[ni]);
                    mma16816(c[mi][ni], al, bh[ni]);
                }
            }
        }
    }

    const int g  = lane >> 2;
    const int tg = lane & 3;
#pragma unroll
    for (int mi = 0; mi < 4; mi++) {
#pragma unroll
        for (int ni = 0; ni < 4; ni++) {
            const int n = bn + wn + ni * 8 + 2 * tg;
            const int m0r = bm + wm + mi * 16 + g;
            if (MODE == 0) {
                const int part = n >> 10;
                const int cc = n & 1023;
                const int h = cc >> 6;
                const int d = cc & 63;
#pragma unroll
                for (int rr = 0; rr < 2; rr++) {
                    const int m = m0r + rr * 8;
                    const int b = m >> 10;
                    const int t = m & 1023;
                    const size_t off = ((size_t)(b * 16 + h) * T_LEN + t) * D_HEAD + d;
                    float2 v = rr ? make_float2(c[mi][ni][2], c[mi][ni][3])
                                  : make_float2(c[mi][ni][0], c[mi][ni][1]);
                    if (part == 0)      *(float2*)(g_q + off) = v;
                    else if (part == 1) *(float2*)(g_k + off) = v;
                    else {
                        uint32_t hi = packbf(v.x, v.y);
                        float hx = __bfloat162float(__float2bfloat16(v.x));
                        float hy = __bfloat162float(__float2bfloat16(v.y));
                        uint32_t lo = packbf(v.x - hx, v.y - hy);
                        *(uint32_t*)(g_vhi + off) = hi;
                        *(uint32_t*)(g_vlo + off) = lo;
                    }
                }
            } else {
                *(float2*)(Cout + (size_t)m0r * C_DIM + n) =
                    make_float2(c[mi][ni][0], c[mi][ni][1]);
                *(float2*)(Cout + (size_t)(m0r + 8) * C_DIM + n) =
                    make_float2(c[mi][ni][2], c[mi][ni][3]);
            }
        }
    }
}

// ---------------------------------------------------------------------------
// Rotary: fast __sincosf
// ---------------------------------------------------------------------------
__global__ __launch_bounds__(256) void rotary_kernel() {
    const int idx = blockIdx.x * blockDim.x + threadIdx.x;
    if (idx >= BH * T_LEN) return;
    const float* qp = g_q + (size_t)idx * D_HEAD;
    const float* kp = g_k + (size_t)idx * D_HEAD;

    float q[64], k[64];
#pragma unroll
    for (int i = 0; i < 16; i++) {
        ((float4*)q)[i] = ((const float4*)qp)[i];
        ((float4*)k)[i] = ((const float4*)kp)[i];
    }
    uint32_t* qh32 = (uint32_t*)g_qhi + (size_t)idx * 32;
    uint32_t* ql32 = (uint32_t*)g_qlo + (size_t)idx * 32;
    uint32_t* kh32 = (uint32_t*)g_khi + (size_t)idx * 32;
    uint32_t* kl32 = (uint32_t*)g_klo + (size_t)idx * 32;

#pragma unroll
    for (int i = 0; i < 32; i++) {
        float qo[2], ko[2];
#pragma unroll
        for (int e = 0; e < 2; e++) {
            const int d = 2 * i + e;
            float cc, sn;
            __sincosf(q[d], &sn, &cc);
            const float rq = (d < 32) ? -q[2 * d + 1] : q[2 * d - 64];
            const float rk = (d < 32) ? -k[2 * d + 1] : k[2 * d - 64];
            qo[e] = q[d] * cc + rq * sn;
            ko[e] = k[d] * cc + rk * sn;
        }
        qh32[i] = packbf(qo[0], qo[1]);
        ql32[i] = packbf(qo[0] - __bfloat162float(__float2bfloat16(qo[0])),
                         qo[1] - __bfloat162float(__float2bfloat16(qo[1])));
        kh32[i] = packbf(ko[0], ko[1]);
        kl32[i] = packbf(ko[0] - __bfloat162float(__float2bfloat16(ko[0])),
                         ko[1] - __bfloat162float(__float2bfloat16(ko[1])));
    }
}

// ---------------------------------------------------------------------------
// Tensor-core flash attention (causal, scale=1.0). Verified round-5 version.
// ---------------------------------------------------------------------------
#define SKE 72
#define SKB (SKE * 2)                // 144
#define ATILE (64 * SKB)             // 9216
#define QTILE (128 * SKB)            // 18432
#define DSMEM_A (2 * QTILE + 8 * ATILE)  // 110592

__global__ __launch_bounds__(256, 1) void attn_mma() {
    extern __shared__ char dsm[];
    const uint32_t sbase = smem_u32(dsm);
    const uint32_t kvbase = sbase + 2 * QTILE;

    const int tid  = threadIdx.x;
    const int lane = tid & 31;
    const int wid  = tid >> 5;
    const int wm   = wid * 16;
    const int bh   = blockIdx.y;
    const int q0   = blockIdx.x * 128;
    const int nt   = 2 * (blockIdx.x + 1);

    {
        const __nv_bfloat16* qs[2] = {g_qhi, g_qlo};
#pragma unroll
        for (int it = 0; it < 8; it++) {
            const int idx = tid + it * 256;
            const int half = idx >> 10;
            const int rem = idx & 1023;
            const int row = rem >> 3;
            const int seg = rem & 7;
            cp16(sbase + (uint32_t)half * QTILE + (uint32_t)row * SKB + seg * 16,
                 qs[half] + ((size_t)(bh * T_LEN + q0 + row) * D_HEAD + seg * 8));
        }
        cp_commit();
    }

    const __nv_bfloat16* kvsrc[4] = {g_khi, g_klo, g_vhi, g_vlo};
    auto issue_kv = [&](int j0, int buf) {
#pragma unroll
        for (int it = 0; it < 8; it++) {
            const int idx = tid + it * 256;
            const int sub = idx >> 9;
            const int rem = idx & 511;
            const int row = rem >> 3;
            const int seg = rem & 7;
            cp16(kvbase + (uint32_t)(buf * 4 + sub) * ATILE + (uint32_t)row * SKB + seg * 16,
                 kvsrc[sub] + ((size_t)(bh * T_LEN + j0 + row) * D_HEAD + seg * 8));
        }
        cp_commit();
    };

    issue_kv(0, 0);

    float o[8][4];
#pragma unroll
    for (int ni = 0; ni < 8; ni++)
#pragma unroll
        for (int e = 0; e < 4; e++) o[ni][e] = 0.f;
    float m0 = -1e30f, m1 = -1e30f, l0 = 0.f, l1 = 0.f;
    uint32_t qh[4][4], ql[4][4];

    const int g  = lane >> 2;
    const int tg = lane & 3;
    const int brow = lane & 7;
    const int bsel = ((lane >> 3) & 1) * 8;

    for (int t = 0; t < nt; t++) {
        const int j0 = t * 64;
        if (t + 1 < nt) { issue_kv((t + 1) * 64, (t + 1) & 1); cp_wait1(); }
        else            { cp_wait0(); }
        __syncthreads();

        if (t == 0) {
            const int arow = lane & 15;
            const int acol = (lane >> 4) << 3;
#pragma unroll
            for (int k16 = 0; k16 < 4; k16++) {
                const uint32_t ad = sbase + (uint32_t)(wm + arow) * SKB
                                  + (uint32_t)(k16 * 16 + acol) * 2;
                ldmat4(qh[k16], ad);
                ldmat4(ql[k16], ad + QTILE);
            }
        }

        const uint32_t kb = kvbase + (uint32_t)((t & 1) * 4) * ATILE;

        float s[8][4];
#pragma unroll
        for (int ni = 0; ni < 8; ni++) {
#pragma unroll
            for (int e = 0; e < 4; e++) s[ni][e] = 0.f;
#pragma unroll
            for (int k16 = 0; k16 < 4; k16++) {
                const uint32_t bd = kb + (uint32_t)(ni * 8 + brow) * SKB
                                  + (uint32_t)(k16 * 16 + bsel) * 2;
                uint32_t kh[2], kl[2];
                ldmat2(kh, bd);
                ldmat2(kl, bd + ATILE);
                mma16816(s[ni], qh[k16], kh);
                mma16816(s[ni], qh[k16], kl);
                mma16816(s[ni], ql[k16], kh);
            }
        }

        if (t >= nt - 2) {
            const int r0 = q0 + wm + g;
#pragma unroll
            for (int ni = 0; ni < 8; ni++) {
                const int cbase = j0 + ni * 8 + 2 * tg;
#pragma unroll
                for (int e = 0; e < 4; e++) {
                    const int col = cbase + (e & 1);
                    const int row = (e < 2) ? r0 : r0 + 8;
                    if (col > row) s[ni][e] = -1e30f;
                }
            }
        }

        float tm0 = -1e30f, tm1 = -1e30f;
#pragma unroll
        for (int ni = 0; ni < 8; ni++) {
            tm0 = fmaxf(tm0, fmaxf(s[ni][0], s[ni][1]));
            tm1 = fmaxf(tm1, fmaxf(s[ni][2], s[ni][3]));
        }
        tm0 = qmax(tm0); tm1 = qmax(tm1);
        const float mn0 = fmaxf(m0, tm0);
        const float mn1 = fmaxf(m1, tm1);
        const float corr0 = __expf(m0 - mn0);
        const float corr1 = __expf(m1 - mn1);
        m0 = mn0; m1 = mn1;

        float ps0 = 0.f, ps1 = 0.f;
#pragma unroll
        for (int ni = 0; ni < 8; ni++) {
            s[ni][0] = __expf(s[ni][0] - m0);
            s[ni][1] = __expf(s[ni][1] - m0);
            s[ni][2] = __expf(s[ni][2] - m1);
            s[ni][3] = __expf(s[ni][3] - m1);
            ps0 += s[ni][0] + s[ni][1];
            ps1 += s[ni][2] + s[ni][3];
        }
        ps0 = qsum(ps0); ps1 = qsum(ps1);
        l0 = l0 * corr0 + ps0;
        l1 = l1 * corr1 + ps1;
#pragma unroll
        for (int ni = 0; ni < 8; ni++) {
            o[ni][0] *= corr0; o[ni][1] *= corr0;
            o[ni][2] *= corr1; o[ni][3] *= corr1;
        }

#pragma unroll
        for (int kj = 0; kj < 4; kj++) {
            uint32_t Ah[4], Al[4];
#pragma unroll
            for (int half = 0; half < 2; half++) {
                const int sn = 2 * kj + half;
                const float p0 = s[sn][0], p1 = s[sn][1];
                const float p2 = s[sn][2], p3 = s[sn][3];
                Ah[2 * half + 0] = packbf(p0, p1);
                Ah[2 * half + 1] = packbf(p2, p3);
                Al[2 * half + 0] = packbf(p0 - __bfloat162float(__float2bfloat16(p0)),
                                          p1 - __bfloat162float(__float2bfloat16(p1)));
                Al[2 * half + 1] = packbf(p2 - __bfloat162float(__float2bfloat16(p2)),
                                          p3 - __bfloat162float(__float2bfloat16(p3)));
            }
            const int vrow = kj * 16 + bsel + brow;
#pragma unroll
            for (int ni = 0; ni < 8; ni++) {
                const uint32_t vd = kb + 2 * ATILE + (uint32_t)vrow * SKB + ni * 16;
                uint32_t vh[2], vl[2];
                ldmat2t(vh, vd);
                ldmat2t(vl, vd + ATILE);
                mma16816(o[ni], Ah, vh);
                mma16816(o[ni], Ah, vl);
                mma16816(o[ni], Al, vh);
            }
        }
        __syncthreads();
    }

    const float inv0 = 1.f / l0;
    const float inv1 = 1.f / l1;
    const int b = bh >> 4;
    const int h = bh & 15;
    const int r0 = q0 + wm + g;
#pragma unroll
    for (int ni = 0; ni < 8; ni++) {
        const int d = ni * 8 + 2 * tg;
#pragma unroll
        for (int rr = 0; rr < 2; rr++) {
            const int row = r0 + rr * 8;
            const float y0 = o[ni][2 * rr + 0] * (rr ? inv1 : inv0);
            const float y1 = o[ni][2 * rr + 1] * (rr ? inv1 : inv0);
            const size_t off = (size_t)(b * T_LEN + row) * C_DIM + h * D_HEAD + d;
            *(uint32_t*)(g_yhi + off) = packbf(y0, y1);
            *(uint32_t*)(g_ylo + off) =
                packbf(y0 - __bfloat162float(__float2bfloat16(y0)),
                       y1 - __bfloat162float(__float2bfloat16(y1)));
        }
    }
}

// ---------------------------------------------------------------------------
extern "C" void kernel_launch(void* const* d_in, const int* in_sizes, int n_in,
                              void* d_out, int out_size) {
    const float* x  = (const float*)d_in[0];   // (8,1024,1024)
    const float* Wa = (const float*)d_in[1];   // (3072,1024)
    const float* Wp = (const float*)d_in[2];   // (1024,1024)
    float* out = (float*)d_out;                // (8,1024,1024)

    cudaFuncSetAttribute(gemm_mma<0>, cudaFuncAttributeMaxDynamicSharedMemorySize, DSMEM);
    cudaFuncSetAttribute(gemm_mma<1>, cudaFuncAttributeMaxDynamicSharedMemorySize, DSMEM);
    cudaFuncSetAttribute(attn_mma, cudaFuncAttributeMaxDynamicSharedMemorySize, DSMEM_A);

    __nv_bfloat16 *xhi, *xlo, *wahi, *walo, *wphi, *wplo, *yhi, *ylo;
    cudaGetSymbolAddress((void**)&xhi,  g_xhi);
    cudaGetSymbolAddress((void**)&xlo,  g_xlo);
    cudaGetSymbolAddress((void**)&wahi, g_wahi);
    cudaGetSymbolAddress((void**)&walo, g_walo);
    cudaGetSymbolAddress((void**)&wphi, g_wphi);
    cudaGetSymbolAddress((void**)&wplo, g_wplo);
    cudaGetSymbolAddress((void**)&yhi,  g_yhi);
    cudaGetSymbolAddress((void**)&ylo,  g_ylo);

    split_kernel<<<(M_ROWS * K_DIM / 4) / 256, 256>>>(x,  xhi,  xlo,  M_ROWS * K_DIM / 4);
    split_kernel<<<(3 * C_DIM * K_DIM / 4) / 256, 256>>>(Wa, wahi, walo, 3 * C_DIM * K_DIM / 4);
    split_kernel<<<(C_DIM * K_DIM / 4) / 256, 256>>>(Wp, wphi, wplo, C_DIM * K_DIM / 4);

    gemm_mma<0><<<dim3(3072 / 128, M_ROWS / 128), 256, DSMEM>>>(xhi, xlo, wahi, walo, nullptr);

    rotary_kernel<<<(BH * T_LEN) / 256, 256>>>();

    attn_mma<<<dim3(T_LEN / 128, BH), 256, DSMEM_A>>>();

    gemm_mma<1><<<dim3(1024 / 128, M_ROWS / 128), 256, DSMEM>>>(yhi, ylo, wphi, wplo, out);
}